// round 1
// baseline (speedup 1.0000x reference)
#include <cuda_runtime.h>
#include <cstdint>
#include <cstdio>

// Problem constants
#define SLEN 1024
#define BSZ  64
#define DMODEL 1024
#define NH   16
#define DKH  64
#define M_TOT (SLEN * BSZ)   // 65536

// Scratch (rules: no cudaMalloc -> __device__ globals). 4 x 256MB.
__device__ float g_q[67108864];
__device__ float g_k[67108864];
__device__ float g_v[67108864];
__device__ float g_c[67108864];

// ---------------------------------------------------------------------------
// SGEMM (NT): C[M,N] = A[M,K] * W[N,K]^T + bias[N]
// 128x128 tile, BK=8, 256 threads, 8x8 per-thread (split 2x2 of 4x4),
// double-buffered shared memory.
// ---------------------------------------------------------------------------
__global__ void __launch_bounds__(256) sgemm_nt(
    const float* __restrict__ A, const float* __restrict__ W,
    const float* __restrict__ bias, float* __restrict__ C,
    int M, int N, int K)
{
    __shared__ float As[2][8][128];
    __shared__ float Ws[2][8][128];

    const int tid = threadIdx.x;
    const int bm = blockIdx.y * 128;
    const int bn = blockIdx.x * 128;

    // loader mapping: each thread loads one float4 from A and one from W
    const int lr = tid >> 1;            // 0..127 (row within tile)
    const int lk = (tid & 1) * 4;       // 0 or 4 (k offset)
    const float* Ag = A + (size_t)(bm + lr) * K + lk;
    const float* Wg = W + (size_t)(bn + lr) * K + lk;

    {
        float4 a4 = *(const float4*)Ag;
        float4 w4 = *(const float4*)Wg;
        As[0][lk + 0][lr] = a4.x; As[0][lk + 1][lr] = a4.y;
        As[0][lk + 2][lr] = a4.z; As[0][lk + 3][lr] = a4.w;
        Ws[0][lk + 0][lr] = w4.x; Ws[0][lk + 1][lr] = w4.y;
        Ws[0][lk + 2][lr] = w4.z; Ws[0][lk + 3][lr] = w4.w;
    }
    __syncthreads();

    const int tx = tid & 15;   // column group
    const int ty = tid >> 4;   // row group

    float acc[8][8];
    #pragma unroll
    for (int i = 0; i < 8; i++)
        #pragma unroll
        for (int j = 0; j < 8; j++)
            acc[i][j] = 0.0f;

    const int ntiles = K >> 3;
    #pragma unroll 1
    for (int t = 0; t < ntiles; t++) {
        const int cur = t & 1;
        float4 na, nw;
        const bool pf = (t + 1 < ntiles);
        if (pf) {
            na = *(const float4*)(Ag + (size_t)(t + 1) * 8);
            nw = *(const float4*)(Wg + (size_t)(t + 1) * 8);
        }
        #pragma unroll
        for (int kk = 0; kk < 8; kk++) {
            float ar[8], wr[8];
            *(float4*)&ar[0] = *(const float4*)&As[cur][kk][ty * 4];
            *(float4*)&ar[4] = *(const float4*)&As[cur][kk][64 + ty * 4];
            *(float4*)&wr[0] = *(const float4*)&Ws[cur][kk][tx * 4];
            *(float4*)&wr[4] = *(const float4*)&Ws[cur][kk][64 + tx * 4];
            #pragma unroll
            for (int i = 0; i < 8; i++)
                #pragma unroll
                for (int j = 0; j < 8; j++)
                    acc[i][j] += ar[i] * wr[j];
        }
        if (pf) {
            const int nxt = 1 - cur;
            As[nxt][lk + 0][lr] = na.x; As[nxt][lk + 1][lr] = na.y;
            As[nxt][lk + 2][lr] = na.z; As[nxt][lk + 3][lr] = na.w;
            Ws[nxt][lk + 0][lr] = nw.x; Ws[nxt][lk + 1][lr] = nw.y;
            Ws[nxt][lk + 2][lr] = nw.z; Ws[nxt][lk + 3][lr] = nw.w;
        }
        __syncthreads();
    }

    // Epilogue: add bias, write float4s
    #pragma unroll
    for (int ih = 0; ih < 2; ih++) {
        #pragma unroll
        for (int i = 0; i < 4; i++) {
            const int r = bm + ih * 64 + ty * 4 + i;
            #pragma unroll
            for (int jh = 0; jh < 2; jh++) {
                const int c = bn + jh * 64 + tx * 4;
                float4 o;
                o.x = acc[ih * 4 + i][jh * 4 + 0] + bias[c + 0];
                o.y = acc[ih * 4 + i][jh * 4 + 1] + bias[c + 1];
                o.z = acc[ih * 4 + i][jh * 4 + 2] + bias[c + 2];
                o.w = acc[ih * 4 + i][jh * 4 + 3] + bias[c + 3];
                *(float4*)(C + (size_t)r * N + c) = o;
            }
        }
    }
}

// ---------------------------------------------------------------------------
// Attention core: one block per (s, h).
//  scores = Q K^T / 8 (masked) ; attn = scores @ V ; softmax over d_k ; store.
// Tiles are 64x64 fp32 in shared memory, LD=68 for alignment + bank spread.
// ---------------------------------------------------------------------------
#define ALD 68

__global__ void __launch_bounds__(256) attn_kernel(
    const float* __restrict__ q, const float* __restrict__ k,
    const float* __restrict__ v, const int* __restrict__ mask,
    float* __restrict__ out)
{
    extern __shared__ float smf[];
    float* Qs = smf;                 // 64*68
    float* Ks = smf + 64 * ALD;
    float* Vs = smf + 2 * 64 * ALD;
    float* Ss = smf + 3 * 64 * ALD;
    __shared__ float s_mv;

    const int s = blockIdx.x;
    const int h = blockIdx.y;
    const int tid = threadIdx.x;
    const size_t base = ((size_t)s * BSZ) * DMODEL + (size_t)h * DKH;

    // Load Q/K/V 64x64 tiles (float4, coalesced within 64-float rows)
    for (int i = tid; i < 64 * 16; i += 256) {
        const int b  = i >> 4;
        const int c4 = (i & 15) << 2;
        const size_t g = base + (size_t)b * DMODEL + c4;
        const float4 qv = *(const float4*)(q + g);
        const float4 kv = *(const float4*)(k + g);
        const float4 vv = *(const float4*)(v + g);
        const int o = b * ALD + c4;
        *(float4*)&Qs[o] = qv;
        *(float4*)&Ks[o] = kv;
        *(float4*)&Vs[o] = vv;
    }
    // mask_val[s] = sum_b src_mask[b][s]^2
    if (tid < 32) {
        int a = 0;
        for (int b = tid; b < 64; b += 32) {
            const int m = mask[b * SLEN + s];
            a += m * m;
        }
        #pragma unroll
        for (int o2 = 16; o2 > 0; o2 >>= 1)
            a += __shfl_xor_sync(0xffffffffu, a, o2);
        if (tid == 0) s_mv = (float)a;
    }
    __syncthreads();
    const bool masked = (s_mv == 0.0f);

    const int tx = tid & 15;   // col group (4 cols)
    const int ty = tid >> 4;   // row group (4 rows)

    // scores = Q K^T / 8
    {
        float acc[4][4];
        #pragma unroll
        for (int i = 0; i < 4; i++)
            #pragma unroll
            for (int j = 0; j < 4; j++) acc[i][j] = 0.0f;

        #pragma unroll 4
        for (int dk = 0; dk < 64; dk += 4) {
            float4 qr[4], kr[4];
            #pragma unroll
            for (int i = 0; i < 4; i++)
                qr[i] = *(const float4*)&Qs[(ty * 4 + i) * ALD + dk];
            #pragma unroll
            for (int j = 0; j < 4; j++)
                kr[j] = *(const float4*)&Ks[(tx * 4 + j) * ALD + dk];
            #pragma unroll
            for (int i = 0; i < 4; i++)
                #pragma unroll
                for (int j = 0; j < 4; j++) {
                    acc[i][j] += qr[i].x * kr[j].x;
                    acc[i][j] += qr[i].y * kr[j].y;
                    acc[i][j] += qr[i].z * kr[j].z;
                    acc[i][j] += qr[i].w * kr[j].w;
                }
        }
        #pragma unroll
        for (int i = 0; i < 4; i++)
            #pragma unroll
            for (int j = 0; j < 4; j++)
                Ss[(ty * 4 + i) * ALD + tx * 4 + j] =
                    masked ? -1e9f : acc[i][j] * 0.125f;
    }
    __syncthreads();

    // attn = scores @ V  (result reuses Qs)
    {
        float acc[4][4];
        #pragma unroll
        for (int i = 0; i < 4; i++)
            #pragma unroll
            for (int j = 0; j < 4; j++) acc[i][j] = 0.0f;

        #pragma unroll 4
        for (int c = 0; c < 64; c += 4) {
            float4 sr[4], vr[4];
            #pragma unroll
            for (int i = 0; i < 4; i++)
                sr[i] = *(const float4*)&Ss[(ty * 4 + i) * ALD + c];
            #pragma unroll
            for (int j = 0; j < 4; j++)
                vr[j] = *(const float4*)&Vs[(c + j) * ALD + tx * 4];
            // note: vr[j] holds V[c+j][tx*4 .. +3]; combine accordingly
            #pragma unroll
            for (int i = 0; i < 4; i++) {
                acc[i][0] += sr[i].x * vr[0].x + sr[i].y * vr[1].x
                           + sr[i].z * vr[2].x + sr[i].w * vr[3].x;
                acc[i][1] += sr[i].x * vr[0].y + sr[i].y * vr[1].y
                           + sr[i].z * vr[2].y + sr[i].w * vr[3].y;
                acc[i][2] += sr[i].x * vr[0].z + sr[i].y * vr[1].z
                           + sr[i].z * vr[2].z + sr[i].w * vr[3].z;
                acc[i][3] += sr[i].x * vr[0].w + sr[i].y * vr[1].w
                           + sr[i].z * vr[2].w + sr[i].w * vr[3].w;
            }
        }
        // Qs fully consumed in the scores phase before last sync -> safe reuse
        #pragma unroll
        for (int i = 0; i < 4; i++)
            #pragma unroll
            for (int j = 0; j < 4; j++)
                Qs[(ty * 4 + i) * ALD + tx * 4 + j] = acc[i][j];
    }
    __syncthreads();

    // softmax over d_k (64) per row, write to concat buffer
    {
        const int lane = tid & 31;
        const int w = tid >> 5;
        for (int b = w; b < 64; b += 8) {
            const float x0 = Qs[b * ALD + lane];
            const float x1 = Qs[b * ALD + 32 + lane];
            float mx = fmaxf(x0, x1);
            #pragma unroll
            for (int o2 = 16; o2 > 0; o2 >>= 1)
                mx = fmaxf(mx, __shfl_xor_sync(0xffffffffu, mx, o2));
            const float e0 = __expf(x0 - mx);
            const float e1 = __expf(x1 - mx);
            float sum = e0 + e1;
            #pragma unroll
            for (int o2 = 16; o2 > 0; o2 >>= 1)
                sum += __shfl_xor_sync(0xffffffffu, sum, o2);
            const float inv = 1.0f / sum;
            const size_t og = base + (size_t)b * DMODEL;
            out[og + lane]      = e0 * inv;
            out[og + 32 + lane] = e1 * inv;
        }
    }
}

// ---------------------------------------------------------------------------
// Launch
// ---------------------------------------------------------------------------
extern "C" void kernel_launch(void* const* d_in, const int* in_sizes, int n_in,
                              void* d_out, int out_size)
{
    const float* K_in = (const float*)d_in[0];
    const float* V_in = (const float*)d_in[1];
    const int*   msk  = (const int*)d_in[2];
    const float* GT   = (const float*)d_in[3];
    const float* Wq   = (const float*)d_in[4];
    const float* bq   = (const float*)d_in[5];
    const float* Wk   = (const float*)d_in[6];
    const float* bk   = (const float*)d_in[7];
    const float* Wv   = (const float*)d_in[8];
    const float* bv   = (const float*)d_in[9];
    const float* Wo   = (const float*)d_in[10];
    const float* bo   = (const float*)d_in[11];
    float* out = (float*)d_out;

    float *gq, *gk, *gv, *gc;
    cudaGetSymbolAddress((void**)&gq, g_q);
    cudaGetSymbolAddress((void**)&gk, g_k);
    cudaGetSymbolAddress((void**)&gv, g_v);
    cudaGetSymbolAddress((void**)&gc, g_c);

    const int attn_smem = 4 * 64 * ALD * (int)sizeof(float);  // 69632 B
    cudaFuncSetAttribute(attn_kernel,
                         cudaFuncAttributeMaxDynamicSharedMemorySize, attn_smem);

    dim3 gg(DMODEL / 128, M_TOT / 128);   // (8, 512)
    dim3 bb(256);

    sgemm_nt<<<gg, bb>>>(GT,   Wq, bq, gq, M_TOT, DMODEL, DMODEL);
    sgemm_nt<<<gg, bb>>>(K_in, Wk, bk, gk, M_TOT, DMODEL, DMODEL);
    sgemm_nt<<<gg, bb>>>(V_in, Wv, bv, gv, M_TOT, DMODEL, DMODEL);
    attn_kernel<<<dim3(SLEN, NH), 256, attn_smem>>>(gq, gk, gv, msk, gc);
    sgemm_nt<<<gg, bb>>>(gc, Wo, bo, out, M_TOT, DMODEL, DMODEL);
}

// round 3
// speedup vs baseline: 1.9136x; 1.9136x over previous
#include <cuda_runtime.h>
#include <cuda_fp16.h>
#include <cstdint>

// Problem constants
#define SLEN 1024
#define BSZ  64
#define DMODEL 1024
#define NH   16
#define DKH  64
#define M_TOT (SLEN * BSZ)   // 65536

// Scratch (no cudaMalloc allowed -> __device__ globals)
__device__ float g_q[67108864];
__device__ float g_k[67108864];
__device__ float g_v[67108864];
__device__ float g_c[67108864];
__device__ __half g_ahi[67108864];   // activation hi (one GEMM at a time)
__device__ __half g_alo[67108864];   // activation lo
__device__ __half g_whi[1048576];    // weight hi
__device__ __half g_wlo[1048576];    // weight lo

// ---------------------------------------------------------------------------
// PTX helpers
// ---------------------------------------------------------------------------
__device__ __forceinline__ uint32_t smem_u32(const void* p) {
    uint32_t a;
    asm("{ .reg .u64 t; cvta.to.shared.u64 t, %1; cvt.u32.u64 %0, t; }"
        : "=r"(a) : "l"(p));
    return a;
}
__device__ __forceinline__ void cp16(uint32_t dst, const void* src) {
    asm volatile("cp.async.cg.shared.global [%0], [%1], 16;"
                 :: "r"(dst), "l"(src));
}
#define CP_COMMIT() asm volatile("cp.async.commit_group;" ::: "memory")
#define CP_WAIT2()  asm volatile("cp.async.wait_group 2;" ::: "memory")
#define CP_WAIT0()  asm volatile("cp.async.wait_group 0;" ::: "memory")

__device__ __forceinline__ void ldsm_x4(uint32_t& r0, uint32_t& r1,
                                        uint32_t& r2, uint32_t& r3, uint32_t a) {
    asm volatile("ldmatrix.sync.aligned.m8n8.x4.shared.b16 {%0,%1,%2,%3}, [%4];"
                 : "=r"(r0), "=r"(r1), "=r"(r2), "=r"(r3) : "r"(a));
}
__device__ __forceinline__ void ldsm_x2(uint32_t& r0, uint32_t& r1, uint32_t a) {
    asm volatile("ldmatrix.sync.aligned.m8n8.x2.shared.b16 {%0,%1}, [%2];"
                 : "=r"(r0), "=r"(r1) : "r"(a));
}
__device__ __forceinline__ void mma16816(float* d, const uint32_t* a,
                                         const uint32_t* b) {
    asm volatile(
        "mma.sync.aligned.m16n8k16.row.col.f32.f16.f16.f32 "
        "{%0,%1,%2,%3}, {%4,%5,%6,%7}, {%8,%9}, {%0,%1,%2,%3};"
        : "+f"(d[0]), "+f"(d[1]), "+f"(d[2]), "+f"(d[3])
        : "r"(a[0]), "r"(a[1]), "r"(a[2]), "r"(a[3]), "r"(b[0]), "r"(b[1]));
}

// ---------------------------------------------------------------------------
// Split fp32 -> (hi, lo) fp16
// ---------------------------------------------------------------------------
__global__ void __launch_bounds__(256) split_fp16(
    const float* __restrict__ in, __half* __restrict__ hi,
    __half* __restrict__ lo, int n4)
{
    const int i = blockIdx.x * blockDim.x + threadIdx.x;
    if (i >= n4) return;
    const float4 v = ((const float4*)in)[i];
    __half h0 = __float2half_rn(v.x);
    __half h1 = __float2half_rn(v.y);
    __half h2 = __float2half_rn(v.z);
    __half h3 = __float2half_rn(v.w);
    __half l0 = __float2half_rn(v.x - __half2float(h0));
    __half l1 = __float2half_rn(v.y - __half2float(h1));
    __half l2 = __float2half_rn(v.z - __half2float(h2));
    __half l3 = __float2half_rn(v.w - __half2float(h3));
    __half2* hp = (__half2*)(hi + (size_t)i * 4);
    __half2* lp = (__half2*)(lo + (size_t)i * 4);
    hp[0] = __halves2half2(h0, h1);
    hp[1] = __halves2half2(h2, h3);
    lp[0] = __halves2half2(l0, l1);
    lp[1] = __halves2half2(l2, l3);
}

// ---------------------------------------------------------------------------
// fp16-split GEMM (NT): C[M,N] = A[M,1024] * W[N,1024]^T + bias
// CTA tile 128x128, 8 warps (2m x 4n), warp tile 64x32.
// K-chunk = 32 halves, 3-stage cp.async pipeline, ldmatrix fragments.
// acc += Ahi*Whi + Ahi*Wlo + Alo*Whi  (fp32 accumulate).
//
// smem per stage: 4 tiles of half[128][40] (row stride 80B, conflict-free
// for both cp.async (16B-aligned) and ldmatrix (rows*80B cover all banks)).
// ---------------------------------------------------------------------------
#define LDH 40                       // halves per smem row
#define TILE_B (128 * LDH * 2)       // 10240 bytes per tile
#define OFF_AHI 0
#define OFF_ALO (TILE_B)
#define OFF_BHI (2 * TILE_B)
#define OFF_BLO (3 * TILE_B)
#define STAGE_B (4 * TILE_B)         // 40960
#define NSTAGE 3
#define GEMM_SMEM (NSTAGE * STAGE_B) // 122880
#define NCHUNK 32

__device__ __forceinline__ void issue_chunk(
    uint32_t stg, const __half* Ahi, const __half* Alo,
    const __half* Bhi, const __half* Blo,
    int bm, int bn, int k0, int tid)
{
    #pragma unroll
    for (int p = 0; p < 2; p++) {
        const int idx = p * 256 + tid;       // 0..511
        const int row = idx >> 2;
        const int q   = idx & 3;
        const uint32_t d = stg + row * (LDH * 2) + q * 16;
        const size_t ga = (size_t)(bm + row) * DMODEL + k0 + q * 8;
        const size_t gb = (size_t)(bn + row) * DMODEL + k0 + q * 8;
        cp16(d + OFF_AHI, Ahi + ga);
        cp16(d + OFF_ALO, Alo + ga);
        cp16(d + OFF_BHI, Bhi + gb);
        cp16(d + OFF_BLO, Blo + gb);
    }
}

__global__ void __launch_bounds__(256, 1) gemm_fp16split(
    const __half* __restrict__ Ahi, const __half* __restrict__ Alo,
    const __half* __restrict__ Bhi, const __half* __restrict__ Blo,
    const float* __restrict__ bias, float* __restrict__ C)
{
    extern __shared__ char smem[];
    const uint32_t sb = smem_u32(smem);
    const int tid = threadIdx.x;
    const int lane = tid & 31;
    const int wid = tid >> 5;
    const int bm = blockIdx.y * 128;
    const int bn = blockIdx.x * 128;
    const int wm = (wid & 1) * 64;
    const int wn = (wid >> 1) * 32;

    float acc[4][4][4];
    #pragma unroll
    for (int i = 0; i < 4; i++)
        #pragma unroll
        for (int j = 0; j < 4; j++)
            #pragma unroll
            for (int x = 0; x < 4; x++) acc[i][j][x] = 0.0f;

    // prologue: stages for chunks 0 and 1
    issue_chunk(sb + 0 * STAGE_B, Ahi, Alo, Bhi, Blo, bm, bn, 0, tid);
    CP_COMMIT();
    issue_chunk(sb + 1 * STAGE_B, Ahi, Alo, Bhi, Blo, bm, bn, 32, tid);
    CP_COMMIT();

    // fragment address components (constant across chunks)
    const int at = lane >> 3, ar = lane & 7;
    const int a_row_off = ((at & 1) << 3) + ar;       // within m16 tile
    const int a_kcol8   = ((at >> 1) << 3);           // 0 or 8
    const int lb = lane & 15;
    const int b_row_off = lb & 7;
    const int b_kcol8   = ((lb >> 3) << 3);

    #pragma unroll 1
    for (int c = 0; c < NCHUNK; c++) {
        if (c + 2 < NCHUNK) {
            issue_chunk(sb + ((c + 2) % NSTAGE) * STAGE_B,
                        Ahi, Alo, Bhi, Blo, bm, bn, (c + 2) * 32, tid);
            CP_COMMIT();
        }
        CP_WAIT2();
        __syncthreads();

        const uint32_t stg = sb + (c % NSTAGE) * STAGE_B;

        #pragma unroll
        for (int ks = 0; ks < 2; ks++) {
            uint32_t ah[4][4], al[4][4], bh[4][2], blr[4][2];
            const int akb = (ks * 16 + a_kcol8) * 2;
            const int bkb = (ks * 16 + b_kcol8) * 2;
            #pragma unroll
            for (int i = 0; i < 4; i++) {
                const uint32_t ra =
                    stg + (wm + i * 16 + a_row_off) * (LDH * 2) + akb;
                ldsm_x4(ah[i][0], ah[i][1], ah[i][2], ah[i][3], ra + OFF_AHI);
                ldsm_x4(al[i][0], al[i][1], al[i][2], al[i][3], ra + OFF_ALO);
            }
            #pragma unroll
            for (int j = 0; j < 4; j++) {
                const uint32_t rb =
                    stg + (wn + j * 8 + b_row_off) * (LDH * 2) + bkb;
                ldsm_x2(bh[j][0], bh[j][1], rb + OFF_BHI);
                ldsm_x2(blr[j][0], blr[j][1], rb + OFF_BLO);
            }
            #pragma unroll
            for (int i = 0; i < 4; i++)
                #pragma unroll
                for (int j = 0; j < 4; j++) {
                    mma16816(acc[i][j], ah[i], bh[j]);
                    mma16816(acc[i][j], ah[i], blr[j]);
                    mma16816(acc[i][j], al[i], bh[j]);
                }
        }
        __syncthreads();
    }

    // epilogue
    #pragma unroll
    for (int i = 0; i < 4; i++) {
        const int r0 = bm + wm + i * 16 + (lane >> 2);
        #pragma unroll
        for (int j = 0; j < 4; j++) {
            const int c0 = bn + wn + j * 8 + ((lane & 3) << 1);
            const float b0 = bias[c0], b1 = bias[c0 + 1];
            float2 v0 = make_float2(acc[i][j][0] + b0, acc[i][j][1] + b1);
            float2 v1 = make_float2(acc[i][j][2] + b0, acc[i][j][3] + b1);
            *(float2*)(C + (size_t)r0 * DMODEL + c0) = v0;
            *(float2*)(C + (size_t)(r0 + 8) * DMODEL + c0) = v1;
        }
    }
}

// ---------------------------------------------------------------------------
// Attention core (unchanged): one block per (s, h).
// ---------------------------------------------------------------------------
#define ALD 68

__global__ void __launch_bounds__(256) attn_kernel(
    const float* __restrict__ q, const float* __restrict__ k,
    const float* __restrict__ v, const int* __restrict__ mask,
    float* __restrict__ out)
{
    extern __shared__ float smf[];
    float* Qs = smf;
    float* Ks = smf + 64 * ALD;
    float* Vs = smf + 2 * 64 * ALD;
    float* Ss = smf + 3 * 64 * ALD;
    __shared__ float s_mv;

    const int s = blockIdx.x;
    const int h = blockIdx.y;
    const int tid = threadIdx.x;
    const size_t base = ((size_t)s * BSZ) * DMODEL + (size_t)h * DKH;

    for (int i = tid; i < 64 * 16; i += 256) {
        const int b  = i >> 4;
        const int c4 = (i & 15) << 2;
        const size_t g = base + (size_t)b * DMODEL + c4;
        const float4 qv = *(const float4*)(q + g);
        const float4 kv = *(const float4*)(k + g);
        const float4 vv = *(const float4*)(v + g);
        const int o = b * ALD + c4;
        *(float4*)&Qs[o] = qv;
        *(float4*)&Ks[o] = kv;
        *(float4*)&Vs[o] = vv;
    }
    if (tid < 32) {
        int a = 0;
        for (int b = tid; b < 64; b += 32) {
            const int m = mask[b * SLEN + s];
            a += m * m;
        }
        #pragma unroll
        for (int o2 = 16; o2 > 0; o2 >>= 1)
            a += __shfl_xor_sync(0xffffffffu, a, o2);
        if (tid == 0) s_mv = (float)a;
    }
    __syncthreads();
    const bool masked = (s_mv == 0.0f);

    const int tx = tid & 15;
    const int ty = tid >> 4;

    {
        float acc[4][4];
        #pragma unroll
        for (int i = 0; i < 4; i++)
            #pragma unroll
            for (int j = 0; j < 4; j++) acc[i][j] = 0.0f;

        #pragma unroll 4
        for (int dk = 0; dk < 64; dk += 4) {
            float4 qr[4], kr[4];
            #pragma unroll
            for (int i = 0; i < 4; i++)
                qr[i] = *(const float4*)&Qs[(ty * 4 + i) * ALD + dk];
            #pragma unroll
            for (int j = 0; j < 4; j++)
                kr[j] = *(const float4*)&Ks[(tx * 4 + j) * ALD + dk];
            #pragma unroll
            for (int i = 0; i < 4; i++)
                #pragma unroll
                for (int j = 0; j < 4; j++) {
                    acc[i][j] += qr[i].x * kr[j].x;
                    acc[i][j] += qr[i].y * kr[j].y;
                    acc[i][j] += qr[i].z * kr[j].z;
                    acc[i][j] += qr[i].w * kr[j].w;
                }
        }
        #pragma unroll
        for (int i = 0; i < 4; i++)
            #pragma unroll
            for (int j = 0; j < 4; j++)
                Ss[(ty * 4 + i) * ALD + tx * 4 + j] =
                    masked ? -1e9f : acc[i][j] * 0.125f;
    }
    __syncthreads();

    {
        float acc[4][4];
        #pragma unroll
        for (int i = 0; i < 4; i++)
            #pragma unroll
            for (int j = 0; j < 4; j++) acc[i][j] = 0.0f;

        #pragma unroll 4
        for (int c = 0; c < 64; c += 4) {
            float4 sr[4], vr[4];
            #pragma unroll
            for (int i = 0; i < 4; i++)
                sr[i] = *(const float4*)&Ss[(ty * 4 + i) * ALD + c];
            #pragma unroll
            for (int j = 0; j < 4; j++)
                vr[j] = *(const float4*)&Vs[(c + j) * ALD + tx * 4];
            #pragma unroll
            for (int i = 0; i < 4; i++) {
                acc[i][0] += sr[i].x * vr[0].x + sr[i].y * vr[1].x
                           + sr[i].z * vr[2].x + sr[i].w * vr[3].x;
                acc[i][1] += sr[i].x * vr[0].y + sr[i].y * vr[1].y
                           + sr[i].z * vr[2].y + sr[i].w * vr[3].y;
                acc[i][2] += sr[i].x * vr[0].z + sr[i].y * vr[1].z
                           + sr[i].z * vr[2].z + sr[i].w * vr[3].z;
                acc[i][3] += sr[i].x * vr[0].w + sr[i].y * vr[1].w
                           + sr[i].z * vr[2].w + sr[i].w * vr[3].w;
            }
        }
        #pragma unroll
        for (int i = 0; i < 4; i++)
            #pragma unroll
            for (int j = 0; j < 4; j++)
                Qs[(ty * 4 + i) * ALD + tx * 4 + j] = acc[i][j];
    }
    __syncthreads();

    {
        const int lane = tid & 31;
        const int w = tid >> 5;
        for (int b = w; b < 64; b += 8) {
            const float x0 = Qs[b * ALD + lane];
            const float x1 = Qs[b * ALD + 32 + lane];
            float mx = fmaxf(x0, x1);
            #pragma unroll
            for (int o2 = 16; o2 > 0; o2 >>= 1)
                mx = fmaxf(mx, __shfl_xor_sync(0xffffffffu, mx, o2));
            const float e0 = __expf(x0 - mx);
            const float e1 = __expf(x1 - mx);
            float sum = e0 + e1;
            #pragma unroll
            for (int o2 = 16; o2 > 0; o2 >>= 1)
                sum += __shfl_xor_sync(0xffffffffu, sum, o2);
            const float inv = 1.0f / sum;
            const size_t og = base + (size_t)b * DMODEL;
            out[og + lane]      = e0 * inv;
            out[og + 32 + lane] = e1 * inv;
        }
    }
}

// ---------------------------------------------------------------------------
// Launch
// ---------------------------------------------------------------------------
extern "C" void kernel_launch(void* const* d_in, const int* in_sizes, int n_in,
                              void* d_out, int out_size)
{
    const float* K_in = (const float*)d_in[0];
    const float* V_in = (const float*)d_in[1];
    const int*   msk  = (const int*)d_in[2];
    const float* GT   = (const float*)d_in[3];
    const float* Wq   = (const float*)d_in[4];
    const float* bq   = (const float*)d_in[5];
    const float* Wk   = (const float*)d_in[6];
    const float* bk   = (const float*)d_in[7];
    const float* Wv   = (const float*)d_in[8];
    const float* bv   = (const float*)d_in[9];
    const float* Wo   = (const float*)d_in[10];
    const float* bo   = (const float*)d_in[11];
    float* out = (float*)d_out;

    float *gq, *gk, *gv, *gc;
    __half *ahi, *alo, *whi, *wlo;
    cudaGetSymbolAddress((void**)&gq, g_q);
    cudaGetSymbolAddress((void**)&gk, g_k);
    cudaGetSymbolAddress((void**)&gv, g_v);
    cudaGetSymbolAddress((void**)&gc, g_c);
    cudaGetSymbolAddress((void**)&ahi, g_ahi);
    cudaGetSymbolAddress((void**)&alo, g_alo);
    cudaGetSymbolAddress((void**)&whi, g_whi);
    cudaGetSymbolAddress((void**)&wlo, g_wlo);

    const int attn_smem = 4 * 64 * ALD * (int)sizeof(float);
    cudaFuncSetAttribute(attn_kernel,
                         cudaFuncAttributeMaxDynamicSharedMemorySize, attn_smem);
    cudaFuncSetAttribute(gemm_fp16split,
                         cudaFuncAttributeMaxDynamicSharedMemorySize, GEMM_SMEM);

    const int ACT4 = M_TOT * DMODEL / 4;       // 16,777,216
    const int W4   = DMODEL * DMODEL / 4;      // 262,144
    dim3 cg_act(ACT4 / 256), cg_w(W4 / 256), cb(256);
    dim3 gg(DMODEL / 128, M_TOT / 128);        // (8, 512)
    dim3 gb(256);

    // Q = GT * Wq^T + bq
    split_fp16<<<cg_act, cb>>>(GT, ahi, alo, ACT4);
    split_fp16<<<cg_w, cb>>>(Wq, whi, wlo, W4);
    gemm_fp16split<<<gg, gb, GEMM_SMEM>>>(ahi, alo, whi, wlo, bq, gq);
    // K = K_in * Wk^T + bk
    split_fp16<<<cg_act, cb>>>(K_in, ahi, alo, ACT4);
    split_fp16<<<cg_w, cb>>>(Wk, whi, wlo, W4);
    gemm_fp16split<<<gg, gb, GEMM_SMEM>>>(ahi, alo, whi, wlo, bk, gk);
    // V = V_in * Wv^T + bv
    split_fp16<<<cg_act, cb>>>(V_in, ahi, alo, ACT4);
    split_fp16<<<cg_w, cb>>>(Wv, whi, wlo, W4);
    gemm_fp16split<<<gg, gb, GEMM_SMEM>>>(ahi, alo, whi, wlo, bv, gv);
    // attention core
    attn_kernel<<<dim3(SLEN, NH), 256, attn_smem>>>(gq, gk, gv, msk, gc);
    // out = concat * Wo^T + bo
    split_fp16<<<cg_act, cb>>>(gc, ahi, alo, ACT4);
    split_fp16<<<cg_w, cb>>>(Wo, whi, wlo, W4);
    gemm_fp16split<<<gg, gb, GEMM_SMEM>>>(ahi, alo, whi, wlo, bo, out);
}

// round 4
// speedup vs baseline: 2.3365x; 1.2210x over previous
#include <cuda_runtime.h>
#include <cuda_fp16.h>
#include <cstdint>

// Problem constants
#define SLEN 1024
#define BSZ  64
#define DMODEL 1024
#define NH   16
#define DKH  64
#define M_TOT (SLEN * BSZ)   // 65536

// Scratch
__device__ float g_q[67108864];
__device__ float g_k[67108864];
__device__ float g_v[67108864];
__device__ float g_c[67108864];
__device__ __half g_whi[1048576];
__device__ __half g_wlo[1048576];

// ---------------------------------------------------------------------------
// PTX helpers
// ---------------------------------------------------------------------------
__device__ __forceinline__ uint32_t smem_u32(const void* p) {
    uint32_t a;
    asm("{ .reg .u64 t; cvta.to.shared.u64 t, %1; cvt.u32.u64 %0, t; }"
        : "=r"(a) : "l"(p));
    return a;
}
__device__ __forceinline__ void cp16(uint32_t dst, const void* src) {
    asm volatile("cp.async.cg.shared.global [%0], [%1], 16;"
                 :: "r"(dst), "l"(src));
}
#define CP_COMMIT() asm volatile("cp.async.commit_group;" ::: "memory")
#define CP_WAIT1()  asm volatile("cp.async.wait_group 1;" ::: "memory")
#define CP_WAIT0()  asm volatile("cp.async.wait_group 0;" ::: "memory")

__device__ __forceinline__ void ldsm_x4(uint32_t& r0, uint32_t& r1,
                                        uint32_t& r2, uint32_t& r3, uint32_t a) {
    asm volatile("ldmatrix.sync.aligned.m8n8.x4.shared.b16 {%0,%1,%2,%3}, [%4];"
                 : "=r"(r0), "=r"(r1), "=r"(r2), "=r"(r3) : "r"(a));
}
__device__ __forceinline__ void mma16816(float* d, const uint32_t* a,
                                         const uint32_t* b) {
    asm volatile(
        "mma.sync.aligned.m16n8k16.row.col.f32.f16.f16.f32 "
        "{%0,%1,%2,%3}, {%4,%5,%6,%7}, {%8,%9}, {%0,%1,%2,%3};"
        : "+f"(d[0]), "+f"(d[1]), "+f"(d[2]), "+f"(d[3])
        : "r"(a[0]), "r"(a[1]), "r"(a[2]), "r"(a[3]), "r"(b[0]), "r"(b[1]));
}

// ---------------------------------------------------------------------------
// Weight split fp32 -> (hi, lo) fp16 (weights only: 1M elements, ~3us)
// ---------------------------------------------------------------------------
__global__ void __launch_bounds__(256) split_fp16(
    const float* __restrict__ in, __half* __restrict__ hi,
    __half* __restrict__ lo, int n4)
{
    const int i = blockIdx.x * blockDim.x + threadIdx.x;
    if (i >= n4) return;
    const float4 v = ((const float4*)in)[i];
    __half h0 = __float2half_rn(v.x);
    __half h1 = __float2half_rn(v.y);
    __half h2 = __float2half_rn(v.z);
    __half h3 = __float2half_rn(v.w);
    __half l0 = __float2half_rn(v.x - __half2float(h0));
    __half l1 = __float2half_rn(v.y - __half2float(h1));
    __half l2 = __float2half_rn(v.z - __half2float(h2));
    __half l3 = __float2half_rn(v.w - __half2float(h3));
    __half2* hp = (__half2*)(hi + (size_t)i * 4);
    __half2* lp = (__half2*)(lo + (size_t)i * 4);
    hp[0] = __halves2half2(h0, h1);
    hp[1] = __halves2half2(h2, h3);
    lp[0] = __halves2half2(l0, l1);
    lp[1] = __halves2half2(l2, l3);
}

// ---------------------------------------------------------------------------
// fp16-split GEMM v2 (NT): C[M,N] = A_f32[M,1024] * W[N,1024]^T + bias
// CTA tile 128x256, 8 warps (2m x 4n), warp tile 64x64.
// A: LDG f32 -> convert hi/lo in-kernel -> STS.  B: pre-split, cp.async.
// 2-stage pipeline, one __syncthreads per chunk.
// acc += Ahi*Whi + Alo*Whi + Ahi*Wlo  (fp32 accumulate).
// ---------------------------------------------------------------------------
#define LDH 40                            // halves per smem row (80B stride)
#define A_TILE_B (128 * LDH * 2)          // 10240
#define B_TILE_B (256 * LDH * 2)          // 20480
#define OFF_ALO  (A_TILE_B)
#define OFF_BHI  (2 * A_TILE_B)
#define OFF_BLO  (2 * A_TILE_B + B_TILE_B)
#define STG_B    (2 * A_TILE_B + 2 * B_TILE_B)   // 61440
#define GEMM_SMEM (2 * STG_B)                    // 122880
#define NCHUNK 32

__device__ __forceinline__ void ldgA(const float* __restrict__ A,
                                     int bm, int k0, int tid, float4* pf)
{
    #pragma unroll
    for (int p = 0; p < 4; p++) {
        const int idx = p * 256 + tid;      // 0..1023
        const int row = idx >> 3;
        const int q   = idx & 7;
        pf[p] = *(const float4*)(A + (size_t)(bm + row) * DMODEL + k0 + q * 4);
    }
}

__device__ __forceinline__ void stsA(char* smem_base, int stg_off,
                                     int tid, const float4* pf)
{
    #pragma unroll
    for (int p = 0; p < 4; p++) {
        const int idx = p * 256 + tid;
        const int row = idx >> 3;
        const int q   = idx & 7;
        const float4 v = pf[p];
        __half2 h01 = __floats2half2_rn(v.x, v.y);
        __half2 h23 = __floats2half2_rn(v.z, v.w);
        __half2 l01 = __floats2half2_rn(v.x - __low2float(h01),
                                        v.y - __high2float(h01));
        __half2 l23 = __floats2half2_rn(v.z - __low2float(h23),
                                        v.w - __high2float(h23));
        char* d = smem_base + stg_off + row * (LDH * 2) + q * 8;
        *(__half2*)(d)             = h01;
        *(__half2*)(d + 4)         = h23;
        *(__half2*)(d + OFF_ALO)     = l01;
        *(__half2*)(d + OFF_ALO + 4) = l23;
    }
}

__device__ __forceinline__ void cpB(uint32_t stg, const __half* __restrict__ Whi,
                                    const __half* __restrict__ Wlo,
                                    int bn, int k0, int tid)
{
    #pragma unroll
    for (int p = 0; p < 4; p++) {
        const int idx = p * 256 + tid;      // 0..1023
        const int row = idx >> 2;           // 0..255
        const int qq  = idx & 3;
        const uint32_t d = stg + OFF_BHI + row * (LDH * 2) + qq * 16;
        const size_t g = (size_t)(bn + row) * DMODEL + k0 + qq * 8;
        cp16(d, Whi + g);
        cp16(d + (OFF_BLO - OFF_BHI), Wlo + g);
    }
}

__global__ void __launch_bounds__(256, 1) gemm_v2(
    const float* __restrict__ A, const __half* __restrict__ Whi,
    const __half* __restrict__ Wlo, const float* __restrict__ bias,
    float* __restrict__ C)
{
    extern __shared__ char smem[];
    const uint32_t sb = smem_u32(smem);
    const int tid = threadIdx.x;
    const int lane = tid & 31;
    const int wid = tid >> 5;
    const int bm = blockIdx.y * 128;
    const int bn = blockIdx.x * 256;
    const int wm = (wid & 1) * 64;
    const int wn = (wid >> 1) * 64;

    float acc[4][8][4];
    #pragma unroll
    for (int i = 0; i < 4; i++)
        #pragma unroll
        for (int j = 0; j < 8; j++)
            #pragma unroll
            for (int x = 0; x < 4; x++) acc[i][j][x] = 0.0f;

    float4 pf[4];

    // prologue
    ldgA(A, bm, 0, tid, pf);
    stsA(smem, 0, tid, pf);
    cpB(sb, Whi, Wlo, bn, 0, tid);
    CP_COMMIT();
    ldgA(A, bm, 32, tid, pf);
    cpB(sb + STG_B, Whi, Wlo, bn, 32, tid);
    CP_COMMIT();
    CP_WAIT1();
    __syncthreads();

    // fragment address components
    const int at = lane >> 3, ar = lane & 7;
    const int a_row_off = ((at & 1) << 3) + ar;
    const int a_kcol8   = ((at >> 1) << 3);
    const int b_row_off = ((lane >> 4) << 3) + (lane & 7);
    const int b_kcol8   = (((lane >> 3) & 1) << 3);

    #pragma unroll 1
    for (int c = 0; c < NCHUNK; c++) {
        const int s = c & 1;
        const uint32_t stg = sb + s * STG_B;

        // ---- compute chunk c ----
        #pragma unroll
        for (int ks = 0; ks < 2; ks++) {
            uint32_t ah[4][4], al[4][4], bf[4][4];
            const int akb = (ks * 16 + a_kcol8) * 2;
            const int bkb = (ks * 16 + b_kcol8) * 2;
            #pragma unroll
            for (int i = 0; i < 4; i++) {
                const uint32_t ra =
                    stg + (wm + i * 16 + a_row_off) * (LDH * 2) + akb;
                ldsm_x4(ah[i][0], ah[i][1], ah[i][2], ah[i][3], ra);
                ldsm_x4(al[i][0], al[i][1], al[i][2], al[i][3], ra + OFF_ALO);
            }
            #pragma unroll
            for (int jj = 0; jj < 4; jj++) {
                const uint32_t rb = stg + OFF_BHI +
                    (wn + jj * 16 + b_row_off) * (LDH * 2) + bkb;
                ldsm_x4(bf[jj][0], bf[jj][1], bf[jj][2], bf[jj][3], rb);
            }
            #pragma unroll
            for (int i = 0; i < 4; i++)
                #pragma unroll
                for (int j = 0; j < 8; j++)
                    mma16816(acc[i][j], ah[i], &bf[j >> 1][(j & 1) * 2]);
            #pragma unroll
            for (int i = 0; i < 4; i++)
                #pragma unroll
                for (int j = 0; j < 8; j++)
                    mma16816(acc[i][j], al[i], &bf[j >> 1][(j & 1) * 2]);
            // reload B lo into bf, third term
            #pragma unroll
            for (int jj = 0; jj < 4; jj++) {
                const uint32_t rb = stg + OFF_BLO +
                    (wn + jj * 16 + b_row_off) * (LDH * 2) + bkb;
                ldsm_x4(bf[jj][0], bf[jj][1], bf[jj][2], bf[jj][3], rb);
            }
            #pragma unroll
            for (int i = 0; i < 4; i++)
                #pragma unroll
                for (int j = 0; j < 8; j++)
                    mma16816(acc[i][j], ah[i], &bf[j >> 1][(j & 1) * 2]);
        }

        // ---- stage chunk c+1 / c+2 ----
        if (c + 1 < NCHUNK) {
            stsA(smem, (s ^ 1) * STG_B, tid, pf);   // A(c+1) -> other stage
            if (c + 2 < NCHUNK)
                ldgA(A, bm, (c + 2) * 32, tid, pf);
        }
        CP_WAIT0();           // B(c+1) landed
        __syncthreads();      // stage s free; A(c+1)/B(c+1) visible
        if (c + 2 < NCHUNK) {
            cpB(stg, Whi, Wlo, bn, (c + 2) * 32, tid);  // into stage s
            CP_COMMIT();
        }
    }

    // epilogue
    #pragma unroll
    for (int i = 0; i < 4; i++) {
        const int r0 = bm + wm + i * 16 + (lane >> 2);
        #pragma unroll
        for (int j = 0; j < 8; j++) {
            const int c0 = bn + wn + j * 8 + ((lane & 3) << 1);
            const float b0 = bias[c0], b1 = bias[c0 + 1];
            float2 v0 = make_float2(acc[i][j][0] + b0, acc[i][j][1] + b1);
            float2 v1 = make_float2(acc[i][j][2] + b0, acc[i][j][3] + b1);
            *(float2*)(C + (size_t)r0 * DMODEL + c0) = v0;
            *(float2*)(C + (size_t)(r0 + 8) * DMODEL + c0) = v1;
        }
    }
}

// ---------------------------------------------------------------------------
// Attention core v2: one block per (s, h), 64 threads, 8x8 register tiles.
// Swizzled smem layout: float4 slot IDX(r,g) = r*16 + ((g + (r>>3)) & 15).
// ---------------------------------------------------------------------------
#define AT_SMEM (4 * 64 * 64 * 4)   // 65536
#define IDX(r, g) (((r) << 4) + ((((g) + ((r) >> 3)) & 15)))

__global__ void __launch_bounds__(64) attn2_kernel(
    const float* __restrict__ q, const float* __restrict__ k,
    const float* __restrict__ v, const int* __restrict__ mask,
    float* __restrict__ out)
{
    extern __shared__ float smf[];
    float4* Qs = (float4*)smf;                 // 1024 float4
    float4* Ks = Qs + 1024;
    float4* Vs = Qs + 2048;
    float4* Ss = Qs + 3072;
    __shared__ float s_mv;

    const int s = blockIdx.x;
    const int h = blockIdx.y;
    const int tid = threadIdx.x;
    const int tx = tid & 7;
    const int ty = tid >> 3;
    const size_t base = ((size_t)s * BSZ) * DMODEL + (size_t)h * DKH;

    // load Q/K/V 64x64 tiles
    #pragma unroll
    for (int p = 0; p < 16; p++) {
        const int i = p * 64 + tid;
        const int b = i >> 4;
        const int g = i & 15;
        const size_t gm = base + (size_t)b * DMODEL + g * 4;
        Qs[IDX(b, g)] = *(const float4*)(q + gm);
        Ks[IDX(b, g)] = *(const float4*)(k + gm);
        Vs[IDX(b, g)] = *(const float4*)(v + gm);
    }
    if (tid < 32) {
        int a = 0;
        #pragma unroll
        for (int b = tid; b < 64; b += 32) {
            const int m = mask[b * SLEN + s];
            a += m * m;
        }
        #pragma unroll
        for (int o2 = 16; o2 > 0; o2 >>= 1)
            a += __shfl_xor_sync(0xffffffffu, a, o2);
        if (tid == 0) s_mv = (float)a;
    }
    __syncthreads();
    const bool masked = (s_mv == 0.0f);

    // phase 1: scores = Q K^T / 8 (masked) -> Ss
    {
        float acc[8][8];
        #pragma unroll
        for (int i = 0; i < 8; i++)
            #pragma unroll
            for (int j = 0; j < 8; j++) acc[i][j] = 0.0f;

        #pragma unroll 2
        for (int g = 0; g < 16; g++) {
            float4 qr[8], kr[8];
            #pragma unroll
            for (int i = 0; i < 8; i++) qr[i] = Qs[IDX(ty * 8 + i, g)];
            #pragma unroll
            for (int j = 0; j < 8; j++) kr[j] = Ks[IDX(tx * 8 + j, g)];
            #pragma unroll
            for (int i = 0; i < 8; i++)
                #pragma unroll
                for (int j = 0; j < 8; j++) {
                    acc[i][j] += qr[i].x * kr[j].x + qr[i].y * kr[j].y
                               + qr[i].z * kr[j].z + qr[i].w * kr[j].w;
                }
        }
        #pragma unroll
        for (int i = 0; i < 8; i++) {
            float4 v0, v1;
            if (masked) {
                v0 = make_float4(-1e9f, -1e9f, -1e9f, -1e9f);
                v1 = v0;
            } else {
                v0 = make_float4(acc[i][0] * 0.125f, acc[i][1] * 0.125f,
                                 acc[i][2] * 0.125f, acc[i][3] * 0.125f);
                v1 = make_float4(acc[i][4] * 0.125f, acc[i][5] * 0.125f,
                                 acc[i][6] * 0.125f, acc[i][7] * 0.125f);
            }
            Ss[IDX(ty * 8 + i, tx * 2)]     = v0;
            Ss[IDX(ty * 8 + i, tx * 2 + 1)] = v1;
        }
    }
    __syncthreads();

    // phase 2: attn = scores @ V -> Qs
    {
        float acc[8][8];
        #pragma unroll
        for (int i = 0; i < 8; i++)
            #pragma unroll
            for (int j = 0; j < 8; j++) acc[i][j] = 0.0f;

        #pragma unroll 2
        for (int g = 0; g < 16; g++) {
            float4 sr[8];
            #pragma unroll
            for (int i = 0; i < 8; i++) sr[i] = Ss[IDX(ty * 8 + i, g)];
            #pragma unroll
            for (int cc = 0; cc < 4; cc++) {
                const float4 vA = Vs[IDX(g * 4 + cc, tx * 2)];
                const float4 vB = Vs[IDX(g * 4 + cc, tx * 2 + 1)];
                #pragma unroll
                for (int i = 0; i < 8; i++) {
                    const float sv = (cc == 0) ? sr[i].x :
                                     (cc == 1) ? sr[i].y :
                                     (cc == 2) ? sr[i].z : sr[i].w;
                    acc[i][0] += sv * vA.x; acc[i][1] += sv * vA.y;
                    acc[i][2] += sv * vA.z; acc[i][3] += sv * vA.w;
                    acc[i][4] += sv * vB.x; acc[i][5] += sv * vB.y;
                    acc[i][6] += sv * vB.z; acc[i][7] += sv * vB.w;
                }
            }
        }
        #pragma unroll
        for (int i = 0; i < 8; i++) {
            Qs[IDX(ty * 8 + i, tx * 2)] =
                make_float4(acc[i][0], acc[i][1], acc[i][2], acc[i][3]);
            Qs[IDX(ty * 8 + i, tx * 2 + 1)] =
                make_float4(acc[i][4], acc[i][5], acc[i][6], acc[i][7]);
        }
    }
    __syncthreads();

    // softmax over d_k (64) per row -> out
    {
        const int lane = tid & 31;
        const int w = tid >> 5;
        const float* Qf = (const float*)Qs;
        for (int b = w; b < 64; b += 2) {
            const int c0 = lane, c1 = lane + 32;
            const float x0 = Qf[IDX(b, c0 >> 2) * 4 + (c0 & 3)];
            const float x1 = Qf[IDX(b, c1 >> 2) * 4 + (c1 & 3)];
            float mx = fmaxf(x0, x1);
            #pragma unroll
            for (int o2 = 16; o2 > 0; o2 >>= 1)
                mx = fmaxf(mx, __shfl_xor_sync(0xffffffffu, mx, o2));
            const float e0 = __expf(x0 - mx);
            const float e1 = __expf(x1 - mx);
            float sum = e0 + e1;
            #pragma unroll
            for (int o2 = 16; o2 > 0; o2 >>= 1)
                sum += __shfl_xor_sync(0xffffffffu, sum, o2);
            const float inv = 1.0f / sum;
            const size_t og = base + (size_t)b * DMODEL;
            out[og + c0] = e0 * inv;
            out[og + c1] = e1 * inv;
        }
    }
}

// ---------------------------------------------------------------------------
// Launch
// ---------------------------------------------------------------------------
extern "C" void kernel_launch(void* const* d_in, const int* in_sizes, int n_in,
                              void* d_out, int out_size)
{
    const float* K_in = (const float*)d_in[0];
    const float* V_in = (const float*)d_in[1];
    const int*   msk  = (const int*)d_in[2];
    const float* GT   = (const float*)d_in[3];
    const float* Wq   = (const float*)d_in[4];
    const float* bq   = (const float*)d_in[5];
    const float* Wk   = (const float*)d_in[6];
    const float* bk   = (const float*)d_in[7];
    const float* Wv   = (const float*)d_in[8];
    const float* bv   = (const float*)d_in[9];
    const float* Wo   = (const float*)d_in[10];
    const float* bo   = (const float*)d_in[11];
    float* out = (float*)d_out;

    float *gq, *gk, *gv, *gc;
    __half *whi, *wlo;
    cudaGetSymbolAddress((void**)&gq, g_q);
    cudaGetSymbolAddress((void**)&gk, g_k);
    cudaGetSymbolAddress((void**)&gv, g_v);
    cudaGetSymbolAddress((void**)&gc, g_c);
    cudaGetSymbolAddress((void**)&whi, g_whi);
    cudaGetSymbolAddress((void**)&wlo, g_wlo);

    cudaFuncSetAttribute(attn2_kernel,
                         cudaFuncAttributeMaxDynamicSharedMemorySize, AT_SMEM);
    cudaFuncSetAttribute(gemm_v2,
                         cudaFuncAttributeMaxDynamicSharedMemorySize, GEMM_SMEM);

    const int W4 = DMODEL * DMODEL / 4;
    dim3 cg_w(W4 / 256), cb(256);
    dim3 gg(DMODEL / 256, M_TOT / 128);   // (4, 512)
    dim3 gb(256);

    split_fp16<<<cg_w, cb>>>(Wq, whi, wlo, W4);
    gemm_v2<<<gg, gb, GEMM_SMEM>>>(GT, whi, wlo, bq, gq);
    split_fp16<<<cg_w, cb>>>(Wk, whi, wlo, W4);
    gemm_v2<<<gg, gb, GEMM_SMEM>>>(K_in, whi, wlo, bk, gk);
    split_fp16<<<cg_w, cb>>>(Wv, whi, wlo, W4);
    gemm_v2<<<gg, gb, GEMM_SMEM>>>(V_in, whi, wlo, bv, gv);
    attn2_kernel<<<dim3(SLEN, NH), 64, AT_SMEM>>>(gq, gk, gv, msk, gc);
    split_fp16<<<cg_w, cb>>>(Wo, whi, wlo, W4);
    gemm_v2<<<gg, gb, GEMM_SMEM>>>(gc, whi, wlo, bo, out);
}

// round 5
// speedup vs baseline: 2.3562x; 1.0084x over previous
#include <cuda_runtime.h>
#include <cuda_fp16.h>
#include <cstdint>

// Problem constants
#define SLEN 1024
#define BSZ  64
#define DMODEL 1024
#define NH   16
#define DKH  64
#define M_TOT (SLEN * BSZ)   // 65536

// Scratch
__device__ float g_q[67108864];
__device__ float g_k[67108864];
__device__ float g_v[67108864];
__device__ float g_c[67108864];
__device__ __half g_whi[1048576];
__device__ __half g_wlo[1048576];

// ---------------------------------------------------------------------------
// PTX helpers
// ---------------------------------------------------------------------------
__device__ __forceinline__ uint32_t smem_u32(const void* p) {
    uint32_t a;
    asm("{ .reg .u64 t; cvta.to.shared.u64 t, %1; cvt.u32.u64 %0, t; }"
        : "=r"(a) : "l"(p));
    return a;
}
__device__ __forceinline__ void cp16(uint32_t dst, const void* src) {
    asm volatile("cp.async.cg.shared.global [%0], [%1], 16;"
                 :: "r"(dst), "l"(src));
}
#define CP_COMMIT() asm volatile("cp.async.commit_group;" ::: "memory")
#define CP_WAIT1()  asm volatile("cp.async.wait_group 1;" ::: "memory")
#define CP_WAIT0()  asm volatile("cp.async.wait_group 0;" ::: "memory")

__device__ __forceinline__ void ldsm_x4(uint32_t& r0, uint32_t& r1,
                                        uint32_t& r2, uint32_t& r3, uint32_t a) {
    asm volatile("ldmatrix.sync.aligned.m8n8.x4.shared.b16 {%0,%1,%2,%3}, [%4];"
                 : "=r"(r0), "=r"(r1), "=r"(r2), "=r"(r3) : "r"(a));
}
__device__ __forceinline__ void mma16816(float* d, const uint32_t* a,
                                         const uint32_t* b) {
    asm volatile(
        "mma.sync.aligned.m16n8k16.row.col.f32.f16.f16.f32 "
        "{%0,%1,%2,%3}, {%4,%5,%6,%7}, {%8,%9}, {%0,%1,%2,%3};"
        : "+f"(d[0]), "+f"(d[1]), "+f"(d[2]), "+f"(d[3])
        : "r"(a[0]), "r"(a[1]), "r"(a[2]), "r"(a[3]), "r"(b[0]), "r"(b[1]));
}

// ---------------------------------------------------------------------------
// Weight split fp32 -> (hi, lo) fp16
// ---------------------------------------------------------------------------
__global__ void __launch_bounds__(256) split_fp16(
    const float* __restrict__ in, __half* __restrict__ hi,
    __half* __restrict__ lo, int n4)
{
    const int i = blockIdx.x * blockDim.x + threadIdx.x;
    if (i >= n4) return;
    const float4 v = ((const float4*)in)[i];
    __half h0 = __float2half_rn(v.x);
    __half h1 = __float2half_rn(v.y);
    __half h2 = __float2half_rn(v.z);
    __half h3 = __float2half_rn(v.w);
    __half l0 = __float2half_rn(v.x - __half2float(h0));
    __half l1 = __float2half_rn(v.y - __half2float(h1));
    __half l2 = __float2half_rn(v.z - __half2float(h2));
    __half l3 = __float2half_rn(v.w - __half2float(h3));
    __half2* hp = (__half2*)(hi + (size_t)i * 4);
    __half2* lp = (__half2*)(lo + (size_t)i * 4);
    hp[0] = __halves2half2(h0, h1);
    hp[1] = __halves2half2(h2, h3);
    lp[0] = __halves2half2(l0, l1);
    lp[1] = __halves2half2(l2, l3);
}

// ---------------------------------------------------------------------------
// fp16-split GEMM v3 (NT): C[M,N] = A_f32[M,1024] * W[N,1024]^T + bias
// CTA tile 128x256, 16 warps (2m x 8n), warp tile 64x32 -> acc 64 regs.
// Fragment reuse: Alo overwrites Ahi registers after Ahi terms complete.
// A: LDG f32 -> split hi/lo -> STS.  B: pre-split, cp.async.
// 2-stage pipeline, one __syncthreads per chunk.
// ---------------------------------------------------------------------------
#define LDH 40                            // halves per smem row (80B stride)
#define A_TILE_B (128 * LDH * 2)          // 10240
#define B_TILE_B (256 * LDH * 2)          // 20480
#define OFF_ALO  (A_TILE_B)
#define OFF_BHI  (2 * A_TILE_B)
#define OFF_BLO  (2 * A_TILE_B + B_TILE_B)
#define STG_B    (2 * A_TILE_B + 2 * B_TILE_B)   // 61440
#define GEMM_SMEM (2 * STG_B)                    // 122880
#define NCHUNK 32
#define GT_THR 512

__device__ __forceinline__ void ldgA(const float* __restrict__ A,
                                     int bm, int k0, int tid, float4* pf)
{
    #pragma unroll
    for (int p = 0; p < 2; p++) {
        const int idx = p * GT_THR + tid;   // 0..1023
        const int row = idx >> 3;
        const int q   = idx & 7;
        pf[p] = *(const float4*)(A + (size_t)(bm + row) * DMODEL + k0 + q * 4);
    }
}

__device__ __forceinline__ void stsA(char* smem_base, int stg_off,
                                     int tid, const float4* pf)
{
    #pragma unroll
    for (int p = 0; p < 2; p++) {
        const int idx = p * GT_THR + tid;
        const int row = idx >> 3;
        const int q   = idx & 7;
        const float4 v = pf[p];
        __half2 h01 = __floats2half2_rn(v.x, v.y);
        __half2 h23 = __floats2half2_rn(v.z, v.w);
        __half2 l01 = __floats2half2_rn(v.x - __low2float(h01),
                                        v.y - __high2float(h01));
        __half2 l23 = __floats2half2_rn(v.z - __low2float(h23),
                                        v.w - __high2float(h23));
        char* d = smem_base + stg_off + row * (LDH * 2) + q * 8;
        *(__half2*)(d)               = h01;
        *(__half2*)(d + 4)           = h23;
        *(__half2*)(d + OFF_ALO)     = l01;
        *(__half2*)(d + OFF_ALO + 4) = l23;
    }
}

__device__ __forceinline__ void cpB(uint32_t stg, const __half* __restrict__ Whi,
                                    const __half* __restrict__ Wlo,
                                    int bn, int k0, int tid)
{
    #pragma unroll
    for (int p = 0; p < 2; p++) {
        const int idx = p * GT_THR + tid;   // 0..1023
        const int row = idx >> 2;           // 0..255
        const int qq  = idx & 3;
        const uint32_t d = stg + OFF_BHI + row * (LDH * 2) + qq * 16;
        const size_t g = (size_t)(bn + row) * DMODEL + k0 + qq * 8;
        cp16(d, Whi + g);
        cp16(d + (OFF_BLO - OFF_BHI), Wlo + g);
    }
}

__global__ void __launch_bounds__(GT_THR, 1) gemm_v3(
    const float* __restrict__ A, const __half* __restrict__ Whi,
    const __half* __restrict__ Wlo, const float* __restrict__ bias,
    float* __restrict__ C)
{
    extern __shared__ char smem[];
    const uint32_t sb = smem_u32(smem);
    const int tid = threadIdx.x;
    const int lane = tid & 31;
    const int wid = tid >> 5;
    const int bm = blockIdx.y * 128;
    const int bn = blockIdx.x * 256;
    const int wm = (wid & 1) * 64;
    const int wn = (wid >> 1) * 32;

    float acc[4][4][4];
    #pragma unroll
    for (int i = 0; i < 4; i++)
        #pragma unroll
        for (int j = 0; j < 4; j++)
            #pragma unroll
            for (int x = 0; x < 4; x++) acc[i][j][x] = 0.0f;

    float4 pf[2];

    // prologue
    ldgA(A, bm, 0, tid, pf);
    stsA(smem, 0, tid, pf);
    cpB(sb, Whi, Wlo, bn, 0, tid);
    CP_COMMIT();
    ldgA(A, bm, 32, tid, pf);
    cpB(sb + STG_B, Whi, Wlo, bn, 32, tid);
    CP_COMMIT();
    CP_WAIT1();
    __syncthreads();

    // fragment address components
    const int at = lane >> 3, ar = lane & 7;
    const int a_row_off = ((at & 1) << 3) + ar;
    const int a_kcol8   = ((at >> 1) << 3);
    const int b_row_off = ((lane >> 4) << 3) + (lane & 7);
    const int b_kcol8   = (((lane >> 3) & 1) << 3);

    #pragma unroll 1
    for (int c = 0; c < NCHUNK; c++) {
        const int s = c & 1;
        const uint32_t stg = sb + s * STG_B;

        // ---- compute chunk c ----
        #pragma unroll
        for (int ks = 0; ks < 2; ks++) {
            uint32_t af[4][4], bh[2][4], bl[2][4];
            const int akb = (ks * 16 + a_kcol8) * 2;
            const int bkb = (ks * 16 + b_kcol8) * 2;
            #pragma unroll
            for (int i = 0; i < 4; i++) {
                const uint32_t ra =
                    stg + (wm + i * 16 + a_row_off) * (LDH * 2) + akb;
                ldsm_x4(af[i][0], af[i][1], af[i][2], af[i][3], ra);
            }
            #pragma unroll
            for (int jj = 0; jj < 2; jj++) {
                const uint32_t rb =
                    stg + (wn + jj * 16 + b_row_off) * (LDH * 2) + bkb;
                ldsm_x4(bh[jj][0], bh[jj][1], bh[jj][2], bh[jj][3],
                        rb + OFF_BHI);
                ldsm_x4(bl[jj][0], bl[jj][1], bl[jj][2], bl[jj][3],
                        rb + OFF_BLO);
            }
            // Ahi * Bhi , Ahi * Blo
            #pragma unroll
            for (int i = 0; i < 4; i++)
                #pragma unroll
                for (int j = 0; j < 4; j++)
                    mma16816(acc[i][j], af[i], &bh[j >> 1][(j & 1) * 2]);
            #pragma unroll
            for (int i = 0; i < 4; i++)
                #pragma unroll
                for (int j = 0; j < 4; j++)
                    mma16816(acc[i][j], af[i], &bl[j >> 1][(j & 1) * 2]);
            // overwrite A frags with Alo, then Alo * Bhi
            #pragma unroll
            for (int i = 0; i < 4; i++) {
                const uint32_t ra =
                    stg + (wm + i * 16 + a_row_off) * (LDH * 2) + akb;
                ldsm_x4(af[i][0], af[i][1], af[i][2], af[i][3],
                        ra + OFF_ALO);
            }
            #pragma unroll
            for (int i = 0; i < 4; i++)
                #pragma unroll
                for (int j = 0; j < 4; j++)
                    mma16816(acc[i][j], af[i], &bh[j >> 1][(j & 1) * 2]);
        }

        // ---- stage chunk c+1 / c+2 ----
        if (c + 1 < NCHUNK) {
            stsA(smem, (s ^ 1) * STG_B, tid, pf);   // A(c+1) -> other stage
            if (c + 2 < NCHUNK)
                ldgA(A, bm, (c + 2) * 32, tid, pf);
        }
        CP_WAIT0();           // B(c+1) landed
        __syncthreads();      // stage s free; A(c+1)/B(c+1) visible
        if (c + 2 < NCHUNK) {
            cpB(stg, Whi, Wlo, bn, (c + 2) * 32, tid);  // into stage s
            CP_COMMIT();
        }
    }

    // epilogue
    #pragma unroll
    for (int i = 0; i < 4; i++) {
        const int r0 = bm + wm + i * 16 + (lane >> 2);
        #pragma unroll
        for (int j = 0; j < 4; j++) {
            const int c0 = bn + wn + j * 8 + ((lane & 3) << 1);
            const float b0 = bias[c0], b1 = bias[c0 + 1];
            float2 v0 = make_float2(acc[i][j][0] + b0, acc[i][j][1] + b1);
            float2 v1 = make_float2(acc[i][j][2] + b0, acc[i][j][3] + b1);
            *(float2*)(C + (size_t)r0 * DMODEL + c0) = v0;
            *(float2*)(C + (size_t)(r0 + 8) * DMODEL + c0) = v1;
        }
    }
}

// ---------------------------------------------------------------------------
// Attention core v2 (unchanged): one block per (s, h), 64 threads.
// ---------------------------------------------------------------------------
#define AT_SMEM (4 * 64 * 64 * 4)   // 65536
#define IDX(r, g) (((r) << 4) + ((((g) + ((r) >> 3)) & 15)))

__global__ void __launch_bounds__(64) attn2_kernel(
    const float* __restrict__ q, const float* __restrict__ k,
    const float* __restrict__ v, const int* __restrict__ mask,
    float* __restrict__ out)
{
    extern __shared__ float smf[];
    float4* Qs = (float4*)smf;
    float4* Ks = Qs + 1024;
    float4* Vs = Qs + 2048;
    float4* Ss = Qs + 3072;
    __shared__ float s_mv;

    const int s = blockIdx.x;
    const int h = blockIdx.y;
    const int tid = threadIdx.x;
    const int tx = tid & 7;
    const int ty = tid >> 3;
    const size_t base = ((size_t)s * BSZ) * DMODEL + (size_t)h * DKH;

    #pragma unroll
    for (int p = 0; p < 16; p++) {
        const int i = p * 64 + tid;
        const int b = i >> 4;
        const int g = i & 15;
        const size_t gm = base + (size_t)b * DMODEL + g * 4;
        Qs[IDX(b, g)] = *(const float4*)(q + gm);
        Ks[IDX(b, g)] = *(const float4*)(k + gm);
        Vs[IDX(b, g)] = *(const float4*)(v + gm);
    }
    if (tid < 32) {
        int a = 0;
        #pragma unroll
        for (int b = tid; b < 64; b += 32) {
            const int m = mask[b * SLEN + s];
            a += m * m;
        }
        #pragma unroll
        for (int o2 = 16; o2 > 0; o2 >>= 1)
            a += __shfl_xor_sync(0xffffffffu, a, o2);
        if (tid == 0) s_mv = (float)a;
    }
    __syncthreads();
    const bool masked = (s_mv == 0.0f);

    {
        float acc[8][8];
        #pragma unroll
        for (int i = 0; i < 8; i++)
            #pragma unroll
            for (int j = 0; j < 8; j++) acc[i][j] = 0.0f;

        #pragma unroll 2
        for (int g = 0; g < 16; g++) {
            float4 qr[8], kr[8];
            #pragma unroll
            for (int i = 0; i < 8; i++) qr[i] = Qs[IDX(ty * 8 + i, g)];
            #pragma unroll
            for (int j = 0; j < 8; j++) kr[j] = Ks[IDX(tx * 8 + j, g)];
            #pragma unroll
            for (int i = 0; i < 8; i++)
                #pragma unroll
                for (int j = 0; j < 8; j++) {
                    acc[i][j] += qr[i].x * kr[j].x + qr[i].y * kr[j].y
                               + qr[i].z * kr[j].z + qr[i].w * kr[j].w;
                }
        }
        #pragma unroll
        for (int i = 0; i < 8; i++) {
            float4 v0, v1;
            if (masked) {
                v0 = make_float4(-1e9f, -1e9f, -1e9f, -1e9f);
                v1 = v0;
            } else {
                v0 = make_float4(acc[i][0] * 0.125f, acc[i][1] * 0.125f,
                                 acc[i][2] * 0.125f, acc[i][3] * 0.125f);
                v1 = make_float4(acc[i][4] * 0.125f, acc[i][5] * 0.125f,
                                 acc[i][6] * 0.125f, acc[i][7] * 0.125f);
            }
            Ss[IDX(ty * 8 + i, tx * 2)]     = v0;
            Ss[IDX(ty * 8 + i, tx * 2 + 1)] = v1;
        }
    }
    __syncthreads();

    {
        float acc[8][8];
        #pragma unroll
        for (int i = 0; i < 8; i++)
            #pragma unroll
            for (int j = 0; j < 8; j++) acc[i][j] = 0.0f;

        #pragma unroll 2
        for (int g = 0; g < 16; g++) {
            float4 sr[8];
            #pragma unroll
            for (int i = 0; i < 8; i++) sr[i] = Ss[IDX(ty * 8 + i, g)];
            #pragma unroll
            for (int cc = 0; cc < 4; cc++) {
                const float4 vA = Vs[IDX(g * 4 + cc, tx * 2)];
                const float4 vB = Vs[IDX(g * 4 + cc, tx * 2 + 1)];
                #pragma unroll
                for (int i = 0; i < 8; i++) {
                    const float sv = (cc == 0) ? sr[i].x :
                                     (cc == 1) ? sr[i].y :
                                     (cc == 2) ? sr[i].z : sr[i].w;
                    acc[i][0] += sv * vA.x; acc[i][1] += sv * vA.y;
                    acc[i][2] += sv * vA.z; acc[i][3] += sv * vA.w;
                    acc[i][4] += sv * vB.x; acc[i][5] += sv * vB.y;
                    acc[i][6] += sv * vB.z; acc[i][7] += sv * vB.w;
                }
            }
        }
        #pragma unroll
        for (int i = 0; i < 8; i++) {
            Qs[IDX(ty * 8 + i, tx * 2)] =
                make_float4(acc[i][0], acc[i][1], acc[i][2], acc[i][3]);
            Qs[IDX(ty * 8 + i, tx * 2 + 1)] =
                make_float4(acc[i][4], acc[i][5], acc[i][6], acc[i][7]);
        }
    }
    __syncthreads();

    {
        const int lane = tid & 31;
        const int w = tid >> 5;
        const float* Qf = (const float*)Qs;
        for (int b = w; b < 64; b += 2) {
            const int c0 = lane, c1 = lane + 32;
            const float x0 = Qf[IDX(b, c0 >> 2) * 4 + (c0 & 3)];
            const float x1 = Qf[IDX(b, c1 >> 2) * 4 + (c1 & 3)];
            float mx = fmaxf(x0, x1);
            #pragma unroll
            for (int o2 = 16; o2 > 0; o2 >>= 1)
                mx = fmaxf(mx, __shfl_xor_sync(0xffffffffu, mx, o2));
            const float e0 = __expf(x0 - mx);
            const float e1 = __expf(x1 - mx);
            float sum = e0 + e1;
            #pragma unroll
            for (int o2 = 16; o2 > 0; o2 >>= 1)
                sum += __shfl_xor_sync(0xffffffffu, sum, o2);
            const float inv = 1.0f / sum;
            const size_t og = base + (size_t)b * DMODEL;
            out[og + c0] = e0 * inv;
            out[og + c1] = e1 * inv;
        }
    }
}

// ---------------------------------------------------------------------------
// Launch
// ---------------------------------------------------------------------------
extern "C" void kernel_launch(void* const* d_in, const int* in_sizes, int n_in,
                              void* d_out, int out_size)
{
    const float* K_in = (const float*)d_in[0];
    const float* V_in = (const float*)d_in[1];
    const int*   msk  = (const int*)d_in[2];
    const float* GT   = (const float*)d_in[3];
    const float* Wq   = (const float*)d_in[4];
    const float* bq   = (const float*)d_in[5];
    const float* Wk   = (const float*)d_in[6];
    const float* bk   = (const float*)d_in[7];
    const float* Wv   = (const float*)d_in[8];
    const float* bv   = (const float*)d_in[9];
    const float* Wo   = (const float*)d_in[10];
    const float* bo   = (const float*)d_in[11];
    float* out = (float*)d_out;

    float *gq, *gk, *gv, *gc;
    __half *whi, *wlo;
    cudaGetSymbolAddress((void**)&gq, g_q);
    cudaGetSymbolAddress((void**)&gk, g_k);
    cudaGetSymbolAddress((void**)&gv, g_v);
    cudaGetSymbolAddress((void**)&gc, g_c);
    cudaGetSymbolAddress((void**)&whi, g_whi);
    cudaGetSymbolAddress((void**)&wlo, g_wlo);

    cudaFuncSetAttribute(attn2_kernel,
                         cudaFuncAttributeMaxDynamicSharedMemorySize, AT_SMEM);
    cudaFuncSetAttribute(gemm_v3,
                         cudaFuncAttributeMaxDynamicSharedMemorySize, GEMM_SMEM);

    const int W4 = DMODEL * DMODEL / 4;
    dim3 cg_w(W4 / 256), cb(256);
    dim3 gg(DMODEL / 256, M_TOT / 128);   // (4, 512)
    dim3 gb(GT_THR);

    split_fp16<<<cg_w, cb>>>(Wq, whi, wlo, W4);
    gemm_v3<<<gg, gb, GEMM_SMEM>>>(GT, whi, wlo, bq, gq);
    split_fp16<<<cg_w, cb>>>(Wk, whi, wlo, W4);
    gemm_v3<<<gg, gb, GEMM_SMEM>>>(K_in, whi, wlo, bk, gk);
    split_fp16<<<cg_w, cb>>>(Wv, whi, wlo, W4);
    gemm_v3<<<gg, gb, GEMM_SMEM>>>(V_in, whi, wlo, bv, gv);
    attn2_kernel<<<dim3(SLEN, NH), 64, AT_SMEM>>>(gq, gk, gv, msk, gc);
    split_fp16<<<cg_w, cb>>>(Wo, whi, wlo, W4);
    gemm_v3<<<gg, gb, GEMM_SMEM>>>(gc, whi, wlo, bo, out);
}

// round 7
// speedup vs baseline: 2.3820x; 1.0110x over previous
#include <cuda_runtime.h>
#include <cuda_fp16.h>
#include <cstdint>

// Problem constants
#define SLEN 1024
#define BSZ  64
#define DMODEL 1024
#define NH   16
#define DKH  64
#define M_TOT (SLEN * BSZ)   // 65536

// Scratch
__device__ float g_q[67108864];
__device__ float g_k[67108864];
__device__ float g_v[67108864];
__device__ float g_c[67108864];
__device__ __half g_whi[1048576];
__device__ __half g_wlo[1048576];

// ---------------------------------------------------------------------------
// PTX helpers
// ---------------------------------------------------------------------------
__device__ __forceinline__ uint32_t smem_u32(const void* p) {
    uint32_t a;
    asm("{ .reg .u64 t; cvta.to.shared.u64 t, %1; cvt.u32.u64 %0, t; }"
        : "=r"(a) : "l"(p));
    return a;
}
__device__ __forceinline__ void cp16(uint32_t dst, const void* src) {
    asm volatile("cp.async.cg.shared.global [%0], [%1], 16;"
                 :: "r"(dst), "l"(src));
}
#define CP_COMMIT() asm volatile("cp.async.commit_group;" ::: "memory")
#define CP_WAIT1()  asm volatile("cp.async.wait_group 1;" ::: "memory")
#define CP_WAIT0()  asm volatile("cp.async.wait_group 0;" ::: "memory")

__device__ __forceinline__ void ldsm_x4(uint32_t& r0, uint32_t& r1,
                                        uint32_t& r2, uint32_t& r3, uint32_t a) {
    asm volatile("ldmatrix.sync.aligned.m8n8.x4.shared.b16 {%0,%1,%2,%3}, [%4];"
                 : "=r"(r0), "=r"(r1), "=r"(r2), "=r"(r3) : "r"(a));
}
__device__ __forceinline__ void mma16816(float* d, const uint32_t* a,
                                         const uint32_t* b) {
    asm volatile(
        "mma.sync.aligned.m16n8k16.row.col.f32.f16.f16.f32 "
        "{%0,%1,%2,%3}, {%4,%5,%6,%7}, {%8,%9}, {%0,%1,%2,%3};"
        : "+f"(d[0]), "+f"(d[1]), "+f"(d[2]), "+f"(d[3])
        : "r"(a[0]), "r"(a[1]), "r"(a[2]), "r"(a[3]), "r"(b[0]), "r"(b[1]));
}

// ---------------------------------------------------------------------------
// Weight split fp32 -> (hi, lo) fp16
// ---------------------------------------------------------------------------
__global__ void __launch_bounds__(256) split_fp16(
    const float* __restrict__ in, __half* __restrict__ hi,
    __half* __restrict__ lo, int n4)
{
    const int i = blockIdx.x * blockDim.x + threadIdx.x;
    if (i >= n4) return;
    const float4 v = ((const float4*)in)[i];
    __half h0 = __float2half_rn(v.x);
    __half h1 = __float2half_rn(v.y);
    __half h2 = __float2half_rn(v.z);
    __half h3 = __float2half_rn(v.w);
    __half l0 = __float2half_rn(v.x - __half2float(h0));
    __half l1 = __float2half_rn(v.y - __half2float(h1));
    __half l2 = __float2half_rn(v.z - __half2float(h2));
    __half l3 = __float2half_rn(v.w - __half2float(h3));
    __half2* hp = (__half2*)(hi + (size_t)i * 4);
    __half2* lp = (__half2*)(lo + (size_t)i * 4);
    hp[0] = __halves2half2(h0, h1);
    hp[1] = __halves2half2(h2, h3);
    lp[0] = __halves2half2(l0, l1);
    lp[1] = __halves2half2(l2, l3);
}

// ---------------------------------------------------------------------------
// fp16-split GEMM v4 (NT): C[M,N] = A_f32[M,1024] * W[N,1024]^T + bias
// CTA tile 128x128, 8 warps (2m x 4n), warp tile 64x32, 256 threads,
// 2 CTAs/SM (80KB smem each). Stage work hoisted ahead of compute so the
// per-chunk serial tail is only wait+bar+cp-issue.
// acc += Ahi*Whi + Ahi*Wlo + Alo*Whi  (fp32 accumulate).
// ---------------------------------------------------------------------------
#define LDH 40                            // halves per smem row (80B stride)
#define A_TILE_B (128 * LDH * 2)          // 10240
#define OFF_ALO  (A_TILE_B)
#define OFF_BHI  (2 * A_TILE_B)
#define OFF_BLO  (3 * A_TILE_B)
#define STG_B    (4 * A_TILE_B)           // 40960
#define GEMM_SMEM (2 * STG_B)             // 81920
#define NCHUNK 32
#define GT_THR 256

__device__ __forceinline__ void ldgA(const float* __restrict__ A,
                                     int bm, int k0, int tid, float4* pf)
{
    #pragma unroll
    for (int p = 0; p < 4; p++) {
        const int idx = p * GT_THR + tid;   // 0..1023
        const int row = idx >> 3;
        const int q   = idx & 7;
        pf[p] = *(const float4*)(A + (size_t)(bm + row) * DMODEL + k0 + q * 4);
    }
}

__device__ __forceinline__ void stsA(char* smem_base, int stg_off,
                                     int tid, const float4* pf)
{
    #pragma unroll
    for (int p = 0; p < 4; p++) {
        const int idx = p * GT_THR + tid;
        const int row = idx >> 3;
        const int q   = idx & 7;
        const float4 v = pf[p];
        __half2 h01 = __floats2half2_rn(v.x, v.y);
        __half2 h23 = __floats2half2_rn(v.z, v.w);
        __half2 l01 = __floats2half2_rn(v.x - __low2float(h01),
                                        v.y - __high2float(h01));
        __half2 l23 = __floats2half2_rn(v.z - __low2float(h23),
                                        v.w - __high2float(h23));
        char* d = smem_base + stg_off + row * (LDH * 2) + q * 8;
        *(__half2*)(d)               = h01;
        *(__half2*)(d + 4)           = h23;
        *(__half2*)(d + OFF_ALO)     = l01;
        *(__half2*)(d + OFF_ALO + 4) = l23;
    }
}

__device__ __forceinline__ void cpB(uint32_t stg, const __half* __restrict__ Whi,
                                    const __half* __restrict__ Wlo,
                                    int bn, int k0, int tid)
{
    #pragma unroll
    for (int p = 0; p < 2; p++) {
        const int idx = p * GT_THR + tid;   // 0..511
        const int row = idx >> 2;           // 0..127
        const int qq  = idx & 3;
        const uint32_t d = stg + OFF_BHI + row * (LDH * 2) + qq * 16;
        const size_t g = (size_t)(bn + row) * DMODEL + k0 + qq * 8;
        cp16(d, Whi + g);
        cp16(d + (OFF_BLO - OFF_BHI), Wlo + g);
    }
}

__global__ void __launch_bounds__(GT_THR, 2) gemm_v4(
    const float* __restrict__ A, const __half* __restrict__ Whi,
    const __half* __restrict__ Wlo, const float* __restrict__ bias,
    float* __restrict__ C)
{
    extern __shared__ char smem[];
    const uint32_t sb = smem_u32(smem);
    const int tid = threadIdx.x;
    const int lane = tid & 31;
    const int wid = tid >> 5;
    const int bm = blockIdx.y * 128;
    const int bn = blockIdx.x * 128;
    const int wm = (wid & 1) * 64;
    const int wn = (wid >> 1) * 32;

    float acc[4][4][4];
    #pragma unroll
    for (int i = 0; i < 4; i++)
        #pragma unroll
        for (int j = 0; j < 4; j++)
            #pragma unroll
            for (int x = 0; x < 4; x++) acc[i][j][x] = 0.0f;

    float4 pf[4];

    // prologue: A(0) into stage0, B(0)/B(1) in flight, pf <- A(1)
    ldgA(A, bm, 0, tid, pf);
    stsA(smem, 0, tid, pf);
    cpB(sb, Whi, Wlo, bn, 0, tid);
    CP_COMMIT();
    ldgA(A, bm, 32, tid, pf);
    cpB(sb + STG_B, Whi, Wlo, bn, 32, tid);
    CP_COMMIT();
    CP_WAIT1();
    __syncthreads();

    // fragment address components
    const int at = lane >> 3, ar = lane & 7;
    const int a_row_off = ((at & 1) << 3) + ar;
    const int a_kcol8   = ((at >> 1) << 3);
    const int b_row_off = ((lane >> 4) << 3) + (lane & 7);
    const int b_kcol8   = (((lane >> 3) & 1) << 3);

    #pragma unroll 1
    for (int c = 0; c < NCHUNK; c++) {
        const int s = c & 1;
        const uint32_t stg = sb + s * STG_B;

        // ---- hoisted stage work (targets stage s^1 / regs only) ----
        if (c + 1 < NCHUNK)
            stsA(smem, (s ^ 1) * STG_B, tid, pf);   // A(c+1)
        if (c + 2 < NCHUNK)
            ldgA(A, bm, (c + 2) * 32, tid, pf);     // A(c+2) -> regs

        // ---- compute chunk c from stage s ----
        #pragma unroll
        for (int ks = 0; ks < 2; ks++) {
            uint32_t af[4][4], bh[2][4], bl[2][4];
            const int akb = (ks * 16 + a_kcol8) * 2;
            const int bkb = (ks * 16 + b_kcol8) * 2;
            #pragma unroll
            for (int i = 0; i < 4; i++) {
                const uint32_t ra =
                    stg + (wm + i * 16 + a_row_off) * (LDH * 2) + akb;
                ldsm_x4(af[i][0], af[i][1], af[i][2], af[i][3], ra);
            }
            #pragma unroll
            for (int jj = 0; jj < 2; jj++) {
                const uint32_t rb =
                    stg + (wn + jj * 16 + b_row_off) * (LDH * 2) + bkb;
                ldsm_x4(bh[jj][0], bh[jj][1], bh[jj][2], bh[jj][3],
                        rb + OFF_BHI);
                ldsm_x4(bl[jj][0], bl[jj][1], bl[jj][2], bl[jj][3],
                        rb + OFF_BLO);
            }
            #pragma unroll
            for (int i = 0; i < 4; i++)
                #pragma unroll
                for (int j = 0; j < 4; j++)
                    mma16816(acc[i][j], af[i], &bh[j >> 1][(j & 1) * 2]);
            #pragma unroll
            for (int i = 0; i < 4; i++)
                #pragma unroll
                for (int j = 0; j < 4; j++)
                    mma16816(acc[i][j], af[i], &bl[j >> 1][(j & 1) * 2]);
            #pragma unroll
            for (int i = 0; i < 4; i++) {
                const uint32_t ra =
                    stg + (wm + i * 16 + a_row_off) * (LDH * 2) + akb;
                ldsm_x4(af[i][0], af[i][1], af[i][2], af[i][3],
                        ra + OFF_ALO);
            }
            #pragma unroll
            for (int i = 0; i < 4; i++)
                #pragma unroll
                for (int j = 0; j < 4; j++)
                    mma16816(acc[i][j], af[i], &bh[j >> 1][(j & 1) * 2]);
        }

        // ---- minimal tail ----
        CP_WAIT0();           // B(c+1) landed
        __syncthreads();      // stage s readers done; A(c+1)/B(c+1) visible
        if (c + 2 < NCHUNK) {
            cpB(stg, Whi, Wlo, bn, (c + 2) * 32, tid);  // into stage s
            CP_COMMIT();
        }
    }

    // epilogue
    #pragma unroll
    for (int i = 0; i < 4; i++) {
        const int r0 = bm + wm + i * 16 + (lane >> 2);
        #pragma unroll
        for (int j = 0; j < 4; j++) {
            const int c0 = bn + wn + j * 8 + ((lane & 3) << 1);
            const float b0 = bias[c0], b1 = bias[c0 + 1];
            float2 v0 = make_float2(acc[i][j][0] + b0, acc[i][j][1] + b1);
            float2 v1 = make_float2(acc[i][j][2] + b0, acc[i][j][3] + b1);
            *(float2*)(C + (size_t)r0 * DMODEL + c0) = v0;
            *(float2*)(C + (size_t)(r0 + 8) * DMODEL + c0) = v1;
        }
    }
}

// ---------------------------------------------------------------------------
// Attention core v2 (unchanged): one block per (s, h), 64 threads.
// ---------------------------------------------------------------------------
#define AT_SMEM (4 * 64 * 64 * 4)   // 65536
#define IDX(r, g) (((r) << 4) + ((((g) + ((r) >> 3)) & 15)))

__global__ void __launch_bounds__(64) attn2_kernel(
    const float* __restrict__ q, const float* __restrict__ k,
    const float* __restrict__ v, const int* __restrict__ mask,
    float* __restrict__ out)
{
    extern __shared__ float smf[];
    float4* Qs = (float4*)smf;
    float4* Ks = Qs + 1024;
    float4* Vs = Qs + 2048;
    float4* Ss = Qs + 3072;
    __shared__ float s_mv;

    const int s = blockIdx.x;
    const int h = blockIdx.y;
    const int tid = threadIdx.x;
    const int tx = tid & 7;
    const int ty = tid >> 3;
    const size_t base = ((size_t)s * BSZ) * DMODEL + (size_t)h * DKH;

    #pragma unroll
    for (int p = 0; p < 16; p++) {
        const int i = p * 64 + tid;
        const int b = i >> 4;
        const int g = i & 15;
        const size_t gm = base + (size_t)b * DMODEL + g * 4;
        Qs[IDX(b, g)] = *(const float4*)(q + gm);
        Ks[IDX(b, g)] = *(const float4*)(k + gm);
        Vs[IDX(b, g)] = *(const float4*)(v + gm);
    }
    if (tid < 32) {
        int a = 0;
        #pragma unroll
        for (int b = tid; b < 64; b += 32) {
            const int m = mask[b * SLEN + s];
            a += m * m;
        }
        #pragma unroll
        for (int o2 = 16; o2 > 0; o2 >>= 1)
            a += __shfl_xor_sync(0xffffffffu, a, o2);
        if (tid == 0) s_mv = (float)a;
    }
    __syncthreads();
    const bool masked = (s_mv == 0.0f);

    {
        float acc[8][8];
        #pragma unroll
        for (int i = 0; i < 8; i++)
            #pragma unroll
            for (int j = 0; j < 8; j++) acc[i][j] = 0.0f;

        #pragma unroll 2
        for (int g = 0; g < 16; g++) {
            float4 qr[8], kr[8];
            #pragma unroll
            for (int i = 0; i < 8; i++) qr[i] = Qs[IDX(ty * 8 + i, g)];
            #pragma unroll
            for (int j = 0; j < 8; j++) kr[j] = Ks[IDX(tx * 8 + j, g)];
            #pragma unroll
            for (int i = 0; i < 8; i++)
                #pragma unroll
                for (int j = 0; j < 8; j++) {
                    acc[i][j] += qr[i].x * kr[j].x + qr[i].y * kr[j].y
                               + qr[i].z * kr[j].z + qr[i].w * kr[j].w;
                }
        }
        #pragma unroll
        for (int i = 0; i < 8; i++) {
            float4 v0, v1;
            if (masked) {
                v0 = make_float4(-1e9f, -1e9f, -1e9f, -1e9f);
                v1 = v0;
            } else {
                v0 = make_float4(acc[i][0] * 0.125f, acc[i][1] * 0.125f,
                                 acc[i][2] * 0.125f, acc[i][3] * 0.125f);
                v1 = make_float4(acc[i][4] * 0.125f, acc[i][5] * 0.125f,
                                 acc[i][6] * 0.125f, acc[i][7] * 0.125f);
            }
            Ss[IDX(ty * 8 + i, tx * 2)]     = v0;
            Ss[IDX(ty * 8 + i, tx * 2 + 1)] = v1;
        }
    }
    __syncthreads();

    {
        float acc[8][8];
        #pragma unroll
        for (int i = 0; i < 8; i++)
            #pragma unroll
            for (int j = 0; j < 8; j++) acc[i][j] = 0.0f;

        #pragma unroll 2
        for (int g = 0; g < 16; g++) {
            float4 sr[8];
            #pragma unroll
            for (int i = 0; i < 8; i++) sr[i] = Ss[IDX(ty * 8 + i, g)];
            #pragma unroll
            for (int cc = 0; cc < 4; cc++) {
                const float4 vA = Vs[IDX(g * 4 + cc, tx * 2)];
                const float4 vB = Vs[IDX(g * 4 + cc, tx * 2 + 1)];
                #pragma unroll
                for (int i = 0; i < 8; i++) {
                    const float sv = (cc == 0) ? sr[i].x :
                                     (cc == 1) ? sr[i].y :
                                     (cc == 2) ? sr[i].z : sr[i].w;
                    acc[i][0] += sv * vA.x; acc[i][1] += sv * vA.y;
                    acc[i][2] += sv * vA.z; acc[i][3] += sv * vA.w;
                    acc[i][4] += sv * vB.x; acc[i][5] += sv * vB.y;
                    acc[i][6] += sv * vB.z; acc[i][7] += sv * vB.w;
                }
            }
        }
        #pragma unroll
        for (int i = 0; i < 8; i++) {
            Qs[IDX(ty * 8 + i, tx * 2)] =
                make_float4(acc[i][0], acc[i][1], acc[i][2], acc[i][3]);
            Qs[IDX(ty * 8 + i, tx * 2 + 1)] =
                make_float4(acc[i][4], acc[i][5], acc[i][6], acc[i][7]);
        }
    }
    __syncthreads();

    {
        const int lane = tid & 31;
        const int w = tid >> 5;
        const float* Qf = (const float*)Qs;
        for (int b = w; b < 64; b += 2) {
            const int c0 = lane, c1 = lane + 32;
            const float x0 = Qf[IDX(b, c0 >> 2) * 4 + (c0 & 3)];
            const float x1 = Qf[IDX(b, c1 >> 2) * 4 + (c1 & 3)];
            float mx = fmaxf(x0, x1);
            #pragma unroll
            for (int o2 = 16; o2 > 0; o2 >>= 1)
                mx = fmaxf(mx, __shfl_xor_sync(0xffffffffu, mx, o2));
            const float e0 = __expf(x0 - mx);
            const float e1 = __expf(x1 - mx);
            float sum = e0 + e1;
            #pragma unroll
            for (int o2 = 16; o2 > 0; o2 >>= 1)
                sum += __shfl_xor_sync(0xffffffffu, sum, o2);
            const float inv = 1.0f / sum;
            const size_t og = base + (size_t)b * DMODEL;
            out[og + c0] = e0 * inv;
            out[og + c1] = e1 * inv;
        }
    }
}

// ---------------------------------------------------------------------------
// Launch
// ---------------------------------------------------------------------------
extern "C" void kernel_launch(void* const* d_in, const int* in_sizes, int n_in,
                              void* d_out, int out_size)
{
    const float* K_in = (const float*)d_in[0];
    const float* V_in = (const float*)d_in[1];
    const int*   msk  = (const int*)d_in[2];
    const float* GT   = (const float*)d_in[3];
    const float* Wq   = (const float*)d_in[4];
    const float* bq   = (const float*)d_in[5];
    const float* Wk   = (const float*)d_in[6];
    const float* bk   = (const float*)d_in[7];
    const float* Wv   = (const float*)d_in[8];
    const float* bv   = (const float*)d_in[9];
    const float* Wo   = (const float*)d_in[10];
    const float* bo   = (const float*)d_in[11];
    float* out = (float*)d_out;

    float *gq, *gk, *gv, *gc;
    __half *whi, *wlo;
    cudaGetSymbolAddress((void**)&gq, g_q);
    cudaGetSymbolAddress((void**)&gk, g_k);
    cudaGetSymbolAddress((void**)&gv, g_v);
    cudaGetSymbolAddress((void**)&gc, g_c);
    cudaGetSymbolAddress((void**)&whi, g_whi);
    cudaGetSymbolAddress((void**)&wlo, g_wlo);

    cudaFuncSetAttribute(attn2_kernel,
                         cudaFuncAttributeMaxDynamicSharedMemorySize, AT_SMEM);
    cudaFuncSetAttribute(gemm_v4,
                         cudaFuncAttributeMaxDynamicSharedMemorySize, GEMM_SMEM);

    const int W4 = DMODEL * DMODEL / 4;
    dim3 cg_w(W4 / 256), cb(256);
    dim3 gg(DMODEL / 128, M_TOT / 128);   // (8, 512)
    dim3 gb(GT_THR);

    split_fp16<<<cg_w, cb>>>(Wq, whi, wlo, W4);
    gemm_v4<<<gg, gb, GEMM_SMEM>>>(GT, whi, wlo, bq, gq);
    split_fp16<<<cg_w, cb>>>(Wk, whi, wlo, W4);
    gemm_v4<<<gg, gb, GEMM_SMEM>>>(K_in, whi, wlo, bk, gk);
    split_fp16<<<cg_w, cb>>>(Wv, whi, wlo, W4);
    gemm_v4<<<gg, gb, GEMM_SMEM>>>(V_in, whi, wlo, bv, gv);
    attn2_kernel<<<dim3(SLEN, NH), 64, AT_SMEM>>>(gq, gk, gv, msk, gc);
    split_fp16<<<cg_w, cb>>>(Wo, whi, wlo, W4);
    gemm_v4<<<gg, gb, GEMM_SMEM>>>(gc, whi, wlo, bo, out);
}

// round 8
// speedup vs baseline: 2.4303x; 1.0203x over previous
#include <cuda_runtime.h>
#include <cuda_fp16.h>
#include <cstdint>

// Problem constants
#define SLEN 1024
#define BSZ  64
#define DMODEL 1024
#define NH   16
#define DKH  64
#define M_TOT (SLEN * BSZ)   // 65536

// Scratch
__device__ float g_q[67108864];
__device__ float g_k[67108864];
__device__ float g_v[67108864];
__device__ float g_c[67108864];
__device__ __half g_whi[1048576];
__device__ __half g_wlo[1048576];

// ---------------------------------------------------------------------------
// PTX helpers
// ---------------------------------------------------------------------------
__device__ __forceinline__ uint32_t smem_u32(const void* p) {
    uint32_t a;
    asm("{ .reg .u64 t; cvta.to.shared.u64 t, %1; cvt.u32.u64 %0, t; }"
        : "=r"(a) : "l"(p));
    return a;
}
__device__ __forceinline__ void cp16(uint32_t dst, const void* src) {
    asm volatile("cp.async.cg.shared.global [%0], [%1], 16;"
                 :: "r"(dst), "l"(src));
}
#define CP_COMMIT() asm volatile("cp.async.commit_group;" ::: "memory")
#define CP_WAIT1()  asm volatile("cp.async.wait_group 1;" ::: "memory")
#define CP_WAIT0()  asm volatile("cp.async.wait_group 0;" ::: "memory")

__device__ __forceinline__ void ldsm_x4(uint32_t& r0, uint32_t& r1,
                                        uint32_t& r2, uint32_t& r3, uint32_t a) {
    asm volatile("ldmatrix.sync.aligned.m8n8.x4.shared.b16 {%0,%1,%2,%3}, [%4];"
                 : "=r"(r0), "=r"(r1), "=r"(r2), "=r"(r3) : "r"(a));
}
__device__ __forceinline__ void mma16816(float* d, const uint32_t* a,
                                         const uint32_t* b) {
    asm volatile(
        "mma.sync.aligned.m16n8k16.row.col.f32.f16.f16.f32 "
        "{%0,%1,%2,%3}, {%4,%5,%6,%7}, {%8,%9}, {%0,%1,%2,%3};"
        : "+f"(d[0]), "+f"(d[1]), "+f"(d[2]), "+f"(d[3])
        : "r"(a[0]), "r"(a[1]), "r"(a[2]), "r"(a[3]), "r"(b[0]), "r"(b[1]));
}

// ---------------------------------------------------------------------------
// Weight split fp32 -> (hi, lo) fp16
// ---------------------------------------------------------------------------
__global__ void __launch_bounds__(256) split_fp16(
    const float* __restrict__ in, __half* __restrict__ hi,
    __half* __restrict__ lo, int n4)
{
    const int i = blockIdx.x * blockDim.x + threadIdx.x;
    if (i >= n4) return;
    const float4 v = ((const float4*)in)[i];
    __half h0 = __float2half_rn(v.x);
    __half h1 = __float2half_rn(v.y);
    __half h2 = __float2half_rn(v.z);
    __half h3 = __float2half_rn(v.w);
    __half l0 = __float2half_rn(v.x - __half2float(h0));
    __half l1 = __float2half_rn(v.y - __half2float(h1));
    __half l2 = __float2half_rn(v.z - __half2float(h2));
    __half l3 = __float2half_rn(v.w - __half2float(h3));
    __half2* hp = (__half2*)(hi + (size_t)i * 4);
    __half2* lp = (__half2*)(lo + (size_t)i * 4);
    hp[0] = __halves2half2(h0, h1);
    hp[1] = __halves2half2(h2, h3);
    lp[0] = __halves2half2(l0, l1);
    lp[1] = __halves2half2(l2, l3);
}

// ---------------------------------------------------------------------------
// fp16-split GEMM v5 (NT): C[M,N] = A_f32[M,1024] * W[N,1024]^T + bias
// CTA tile 128x256, 16 warps (2m x 8n), warp tile 64x32, KC=64 (16 chunks).
// 2 stages x 108KB = 216KB smem, 1 CTA/SM. Hoisted staging; per-chunk tail
// is only wait+bar+cp-issue, amortized over 2x the MMAs of KC=32.
// acc += Ahi*Whi + Ahi*Wlo + Alo*Whi  (fp32 accumulate).
// ---------------------------------------------------------------------------
#define KC 64
#define LDH 72                            // halves per smem row (144B stride)
#define ROWB (LDH * 2)                    // 144
#define A_TILE_B (128 * ROWB)             // 18432
#define B_TILE_B (256 * ROWB)             // 36864
#define OFF_ALO  (A_TILE_B)
#define OFF_BHI  (2 * A_TILE_B)
#define OFF_BLO  (2 * A_TILE_B + B_TILE_B)
#define STG_B    (2 * A_TILE_B + 2 * B_TILE_B)   // 110592
#define GEMM_SMEM (2 * STG_B)                    // 221184
#define NCHUNK 16
#define GT_THR 512

__device__ __forceinline__ void ldgA(const float* __restrict__ A,
                                     int bm, int k0, int tid, float4* pf)
{
    #pragma unroll
    for (int p = 0; p < 4; p++) {
        const int idx = p * GT_THR + tid;   // 0..2047
        const int row = idx >> 4;           // 0..127
        const int q   = idx & 15;           // 16 float4 per 64-f32 row
        pf[p] = *(const float4*)(A + (size_t)(bm + row) * DMODEL + k0 + q * 4);
    }
}

__device__ __forceinline__ void stsA(char* smem_base, int stg_off,
                                     int tid, const float4* pf)
{
    #pragma unroll
    for (int p = 0; p < 4; p++) {
        const int idx = p * GT_THR + tid;
        const int row = idx >> 4;
        const int q   = idx & 15;
        const float4 v = pf[p];
        __half2 h01 = __floats2half2_rn(v.x, v.y);
        __half2 h23 = __floats2half2_rn(v.z, v.w);
        __half2 l01 = __floats2half2_rn(v.x - __low2float(h01),
                                        v.y - __high2float(h01));
        __half2 l23 = __floats2half2_rn(v.z - __low2float(h23),
                                        v.w - __high2float(h23));
        char* d = smem_base + stg_off + row * ROWB + q * 8;
        *(__half2*)(d)               = h01;
        *(__half2*)(d + 4)           = h23;
        *(__half2*)(d + OFF_ALO)     = l01;
        *(__half2*)(d + OFF_ALO + 4) = l23;
    }
}

__device__ __forceinline__ void cpB(uint32_t stg, const __half* __restrict__ Whi,
                                    const __half* __restrict__ Wlo,
                                    int bn, int k0, int tid)
{
    #pragma unroll
    for (int p = 0; p < 4; p++) {
        const int idx = p * GT_THR + tid;   // 0..2047
        const int row = idx >> 3;           // 0..255
        const int qq  = idx & 7;            // 8 x 16B per 64-half row
        const uint32_t d = stg + OFF_BHI + row * ROWB + qq * 16;
        const size_t g = (size_t)(bn + row) * DMODEL + k0 + qq * 8;
        cp16(d, Whi + g);
        cp16(d + (OFF_BLO - OFF_BHI), Wlo + g);
    }
}

__global__ void __launch_bounds__(GT_THR, 1) gemm_v5(
    const float* __restrict__ A, const __half* __restrict__ Whi,
    const __half* __restrict__ Wlo, const float* __restrict__ bias,
    float* __restrict__ C)
{
    extern __shared__ char smem[];
    const uint32_t sb = smem_u32(smem);
    const int tid = threadIdx.x;
    const int lane = tid & 31;
    const int wid = tid >> 5;
    const int bm = blockIdx.y * 128;
    const int bn = blockIdx.x * 256;
    const int wm = (wid & 1) * 64;
    const int wn = (wid >> 1) * 32;

    float acc[4][4][4];
    #pragma unroll
    for (int i = 0; i < 4; i++)
        #pragma unroll
        for (int j = 0; j < 4; j++)
            #pragma unroll
            for (int x = 0; x < 4; x++) acc[i][j][x] = 0.0f;

    float4 pf[4];

    // prologue: A(0) -> stage0, B(0)/B(1) in flight, pf <- A(1)
    ldgA(A, bm, 0, tid, pf);
    stsA(smem, 0, tid, pf);
    cpB(sb, Whi, Wlo, bn, 0, tid);
    CP_COMMIT();
    ldgA(A, bm, KC, tid, pf);
    cpB(sb + STG_B, Whi, Wlo, bn, KC, tid);
    CP_COMMIT();
    CP_WAIT1();
    __syncthreads();

    // fragment address components
    const int at = lane >> 3, ar = lane & 7;
    const int a_row_off = ((at & 1) << 3) + ar;
    const int a_kcol8   = ((at >> 1) << 3);
    const int b_row_off = ((lane >> 4) << 3) + (lane & 7);
    const int b_kcol8   = (((lane >> 3) & 1) << 3);

    #pragma unroll 1
    for (int c = 0; c < NCHUNK; c++) {
        const int s = c & 1;
        const uint32_t stg = sb + s * STG_B;

        // ---- hoisted stage work (targets stage s^1 / regs only) ----
        if (c + 1 < NCHUNK)
            stsA(smem, (s ^ 1) * STG_B, tid, pf);   // A(c+1)
        if (c + 2 < NCHUNK)
            ldgA(A, bm, (c + 2) * KC, tid, pf);     // A(c+2) -> regs

        // ---- compute chunk c from stage s: 4 k-steps of 16 ----
        #pragma unroll
        for (int ks = 0; ks < 4; ks++) {
            uint32_t af[4][4], bh[2][4], bl[2][4];
            const int akb = (ks * 16 + a_kcol8) * 2;
            const int bkb = (ks * 16 + b_kcol8) * 2;
            #pragma unroll
            for (int i = 0; i < 4; i++) {
                const uint32_t ra =
                    stg + (wm + i * 16 + a_row_off) * ROWB + akb;
                ldsm_x4(af[i][0], af[i][1], af[i][2], af[i][3], ra);
            }
            #pragma unroll
            for (int jj = 0; jj < 2; jj++) {
                const uint32_t rb =
                    stg + (wn + jj * 16 + b_row_off) * ROWB + bkb;
                ldsm_x4(bh[jj][0], bh[jj][1], bh[jj][2], bh[jj][3],
                        rb + OFF_BHI);
                ldsm_x4(bl[jj][0], bl[jj][1], bl[jj][2], bl[jj][3],
                        rb + OFF_BLO);
            }
            #pragma unroll
            for (int i = 0; i < 4; i++)
                #pragma unroll
                for (int j = 0; j < 4; j++)
                    mma16816(acc[i][j], af[i], &bh[j >> 1][(j & 1) * 2]);
            #pragma unroll
            for (int i = 0; i < 4; i++)
                #pragma unroll
                for (int j = 0; j < 4; j++)
                    mma16816(acc[i][j], af[i], &bl[j >> 1][(j & 1) * 2]);
            #pragma unroll
            for (int i = 0; i < 4; i++) {
                const uint32_t ra =
                    stg + (wm + i * 16 + a_row_off) * ROWB + akb;
                ldsm_x4(af[i][0], af[i][1], af[i][2], af[i][3],
                        ra + OFF_ALO);
            }
            #pragma unroll
            for (int i = 0; i < 4; i++)
                #pragma unroll
                for (int j = 0; j < 4; j++)
                    mma16816(acc[i][j], af[i], &bh[j >> 1][(j & 1) * 2]);
        }

        // ---- minimal tail ----
        CP_WAIT0();           // B(c+1) landed
        __syncthreads();      // stage s readers done; A(c+1)/B(c+1) visible
        if (c + 2 < NCHUNK) {
            cpB(stg, Whi, Wlo, bn, (c + 2) * KC, tid);  // into stage s
            CP_COMMIT();
        }
    }

    // epilogue
    #pragma unroll
    for (int i = 0; i < 4; i++) {
        const int r0 = bm + wm + i * 16 + (lane >> 2);
        #pragma unroll
        for (int j = 0; j < 4; j++) {
            const int c0 = bn + wn + j * 8 + ((lane & 3) << 1);
            const float b0 = bias[c0], b1 = bias[c0 + 1];
            float2 v0 = make_float2(acc[i][j][0] + b0, acc[i][j][1] + b1);
            float2 v1 = make_float2(acc[i][j][2] + b0, acc[i][j][3] + b1);
            *(float2*)(C + (size_t)r0 * DMODEL + c0) = v0;
            *(float2*)(C + (size_t)(r0 + 8) * DMODEL + c0) = v1;
        }
    }
}

// ---------------------------------------------------------------------------
// Attention core v3: one block per (s, h), 128 threads, 4x8 register tiles.
// Swizzled smem: float4 slot IDX(r,g) = r*16 + ((g + (r>>3)) & 15).
// ---------------------------------------------------------------------------
#define AT_SMEM (4 * 64 * 64 * 4)   // 65536
#define IDX(r, g) (((r) << 4) + ((((g) + ((r) >> 3)) & 15)))

__global__ void __launch_bounds__(128) attn3_kernel(
    const float* __restrict__ q, const float* __restrict__ k,
    const float* __restrict__ v, const int* __restrict__ mask,
    float* __restrict__ out)
{
    extern __shared__ float smf[];
    float4* Qs = (float4*)smf;
    float4* Ks = Qs + 1024;
    float4* Vs = Qs + 2048;
    float4* Ss = Qs + 3072;
    __shared__ float s_mv;

    const int s = blockIdx.x;
    const int h = blockIdx.y;
    const int tid = threadIdx.x;
    const int tx = tid & 7;       // 8 col groups (8 cols each)
    const int ty = tid >> 3;      // 16 row groups (4 rows each)
    const size_t base = ((size_t)s * BSZ) * DMODEL + (size_t)h * DKH;

    #pragma unroll
    for (int p = 0; p < 8; p++) {
        const int i = p * 128 + tid;
        const int b = i >> 4;
        const int g = i & 15;
        const size_t gm = base + (size_t)b * DMODEL + g * 4;
        Qs[IDX(b, g)] = *(const float4*)(q + gm);
        Ks[IDX(b, g)] = *(const float4*)(k + gm);
        Vs[IDX(b, g)] = *(const float4*)(v + gm);
    }
    if (tid < 32) {
        int a = 0;
        #pragma unroll
        for (int b = tid; b < 64; b += 32) {
            const int m = mask[b * SLEN + s];
            a += m * m;
        }
        #pragma unroll
        for (int o2 = 16; o2 > 0; o2 >>= 1)
            a += __shfl_xor_sync(0xffffffffu, a, o2);
        if (tid == 0) s_mv = (float)a;
    }
    __syncthreads();
    const bool masked = (s_mv == 0.0f);

    // phase 1: scores = Q K^T / 8 (masked) -> Ss
    {
        float acc[4][8];
        #pragma unroll
        for (int i = 0; i < 4; i++)
            #pragma unroll
            for (int j = 0; j < 8; j++) acc[i][j] = 0.0f;

        #pragma unroll 2
        for (int g = 0; g < 16; g++) {
            float4 qr[4], kr[8];
            #pragma unroll
            for (int i = 0; i < 4; i++) qr[i] = Qs[IDX(ty * 4 + i, g)];
            #pragma unroll
            for (int j = 0; j < 8; j++) kr[j] = Ks[IDX(tx * 8 + j, g)];
            #pragma unroll
            for (int i = 0; i < 4; i++)
                #pragma unroll
                for (int j = 0; j < 8; j++) {
                    acc[i][j] += qr[i].x * kr[j].x + qr[i].y * kr[j].y
                               + qr[i].z * kr[j].z + qr[i].w * kr[j].w;
                }
        }
        #pragma unroll
        for (int i = 0; i < 4; i++) {
            float4 v0, v1;
            if (masked) {
                v0 = make_float4(-1e9f, -1e9f, -1e9f, -1e9f);
                v1 = v0;
            } else {
                v0 = make_float4(acc[i][0] * 0.125f, acc[i][1] * 0.125f,
                                 acc[i][2] * 0.125f, acc[i][3] * 0.125f);
                v1 = make_float4(acc[i][4] * 0.125f, acc[i][5] * 0.125f,
                                 acc[i][6] * 0.125f, acc[i][7] * 0.125f);
            }
            Ss[IDX(ty * 4 + i, tx * 2)]     = v0;
            Ss[IDX(ty * 4 + i, tx * 2 + 1)] = v1;
        }
    }
    __syncthreads();

    // phase 2: attn = scores @ V -> Qs
    {
        float acc[4][8];
        #pragma unroll
        for (int i = 0; i < 4; i++)
            #pragma unroll
            for (int j = 0; j < 8; j++) acc[i][j] = 0.0f;

        #pragma unroll 2
        for (int g = 0; g < 16; g++) {
            float4 sr[4];
            #pragma unroll
            for (int i = 0; i < 4; i++) sr[i] = Ss[IDX(ty * 4 + i, g)];
            #pragma unroll
            for (int cc = 0; cc < 4; cc++) {
                const float4 vA = Vs[IDX(g * 4 + cc, tx * 2)];
                const float4 vB = Vs[IDX(g * 4 + cc, tx * 2 + 1)];
                #pragma unroll
                for (int i = 0; i < 4; i++) {
                    const float sv = (cc == 0) ? sr[i].x :
                                     (cc == 1) ? sr[i].y :
                                     (cc == 2) ? sr[i].z : sr[i].w;
                    acc[i][0] += sv * vA.x; acc[i][1] += sv * vA.y;
                    acc[i][2] += sv * vA.z; acc[i][3] += sv * vA.w;
                    acc[i][4] += sv * vB.x; acc[i][5] += sv * vB.y;
                    acc[i][6] += sv * vB.z; acc[i][7] += sv * vB.w;
                }
            }
        }
        #pragma unroll
        for (int i = 0; i < 4; i++) {
            Qs[IDX(ty * 4 + i, tx * 2)] =
                make_float4(acc[i][0], acc[i][1], acc[i][2], acc[i][3]);
            Qs[IDX(ty * 4 + i, tx * 2 + 1)] =
                make_float4(acc[i][4], acc[i][5], acc[i][6], acc[i][7]);
        }
    }
    __syncthreads();

    // softmax over d_k (64) per row -> out
    {
        const int lane = tid & 31;
        const int w = tid >> 5;
        const float* Qf = (const float*)Qs;
        for (int b = w; b < 64; b += 4) {
            const int c0 = lane, c1 = lane + 32;
            const float x0 = Qf[IDX(b, c0 >> 2) * 4 + (c0 & 3)];
            const float x1 = Qf[IDX(b, c1 >> 2) * 4 + (c1 & 3)];
            float mx = fmaxf(x0, x1);
            #pragma unroll
            for (int o2 = 16; o2 > 0; o2 >>= 1)
                mx = fmaxf(mx, __shfl_xor_sync(0xffffffffu, mx, o2));
            const float e0 = __expf(x0 - mx);
            const float e1 = __expf(x1 - mx);
            float sum = e0 + e1;
            #pragma unroll
            for (int o2 = 16; o2 > 0; o2 >>= 1)
                sum += __shfl_xor_sync(0xffffffffu, sum, o2);
            const float inv = 1.0f / sum;
            const size_t og = base + (size_t)b * DMODEL;
            out[og + c0] = e0 * inv;
            out[og + c1] = e1 * inv;
        }
    }
}

// ---------------------------------------------------------------------------
// Launch
// ---------------------------------------------------------------------------
extern "C" void kernel_launch(void* const* d_in, const int* in_sizes, int n_in,
                              void* d_out, int out_size)
{
    const float* K_in = (const float*)d_in[0];
    const float* V_in = (const float*)d_in[1];
    const int*   msk  = (const int*)d_in[2];
    const float* GT   = (const float*)d_in[3];
    const float* Wq   = (const float*)d_in[4];
    const float* bq   = (const float*)d_in[5];
    const float* Wk   = (const float*)d_in[6];
    const float* bk   = (const float*)d_in[7];
    const float* Wv   = (const float*)d_in[8];
    const float* bv   = (const float*)d_in[9];
    const float* Wo   = (const float*)d_in[10];
    const float* bo   = (const float*)d_in[11];
    float* out = (float*)d_out;

    float *gq, *gk, *gv, *gc;
    __half *whi, *wlo;
    cudaGetSymbolAddress((void**)&gq, g_q);
    cudaGetSymbolAddress((void**)&gk, g_k);
    cudaGetSymbolAddress((void**)&gv, g_v);
    cudaGetSymbolAddress((void**)&gc, g_c);
    cudaGetSymbolAddress((void**)&whi, g_whi);
    cudaGetSymbolAddress((void**)&wlo, g_wlo);

    cudaFuncSetAttribute(attn3_kernel,
                         cudaFuncAttributeMaxDynamicSharedMemorySize, AT_SMEM);
    cudaFuncSetAttribute(gemm_v5,
                         cudaFuncAttributeMaxDynamicSharedMemorySize, GEMM_SMEM);

    const int W4 = DMODEL * DMODEL / 4;
    dim3 cg_w(W4 / 256), cb(256);
    dim3 gg(DMODEL / 256, M_TOT / 128);   // (4, 512)
    dim3 gb(GT_THR);

    split_fp16<<<cg_w, cb>>>(Wq, whi, wlo, W4);
    gemm_v5<<<gg, gb, GEMM_SMEM>>>(GT, whi, wlo, bq, gq);
    split_fp16<<<cg_w, cb>>>(Wk, whi, wlo, W4);
    gemm_v5<<<gg, gb, GEMM_SMEM>>>(K_in, whi, wlo, bk, gk);
    split_fp16<<<cg_w, cb>>>(Wv, whi, wlo, W4);
    gemm_v5<<<gg, gb, GEMM_SMEM>>>(V_in, whi, wlo, bv, gv);
    attn3_kernel<<<dim3(SLEN, NH), 128, AT_SMEM>>>(gq, gk, gv, msk, gc);
    split_fp16<<<cg_w, cb>>>(Wo, whi, wlo, W4);
    gemm_v5<<<gg, gb, GEMM_SMEM>>>(gc, whi, wlo, bo, out);
}